// round 1
// baseline (speedup 1.0000x reference)
#include <cuda_runtime.h>

#define D_MODEL   1024
#define NUM_HEADS 16
#define HEAD_DIM  64
#define SEQ       2048
#define BATCH     2
#define MTOT      (BATCH*SEQ)   /* 4096 */

// Scratch (allocation-free rule: __device__ globals). 4 x 16 MB.
__device__ float g_Q[(size_t)MTOT * D_MODEL];
__device__ float g_K[(size_t)MTOT * D_MODEL];
__device__ float g_V[(size_t)MTOT * D_MODEL];
__device__ float g_ctx[(size_t)MTOT * D_MODEL];

// C[m,n] = sum_k A[m,k] * W[n,k] + bias[n]
// A: [MTOT,1024] row-major. W: [1024,1024] row-major (we need x @ W^T).
// headsplit=1: write to [B,H,S,d] layout; 0: plain [m, n].
__global__ __launch_bounds__(256) void gemm_nt_kernel(
    const float* __restrict__ A, const float* __restrict__ W,
    const float* __restrict__ bias, float* __restrict__ C, int headsplit)
{
    const int bm = blockIdx.x;   // M / 128
    const int bn = blockIdx.y;   // N / 128
    __shared__ float As[16][128];
    __shared__ float Bs[16][128];
    const int t  = threadIdx.x;
    const int ty = t >> 4, tx = t & 15;

    float acc[8][8];
#pragma unroll
    for (int u = 0; u < 8; u++)
#pragma unroll
        for (int v = 0; v < 8; v++) acc[u][v] = 0.f;

    const float* Aptr = A + (size_t)(bm * 128) * 1024;
    const float* Wptr = W + (size_t)(bn * 128) * 1024;

    for (int k0 = 0; k0 < 1024; k0 += 16) {
#pragma unroll
        for (int l = 0; l < 2; l++) {
            int idx = t + l * 256;        // 0..511 float4 slots
            int row = idx >> 2;           // 0..127
            int c4  = (idx & 3) * 4;      // 0,4,8,12
            float4 av = *(const float4*)(Aptr + (size_t)row * 1024 + k0 + c4);
            As[c4 + 0][row] = av.x; As[c4 + 1][row] = av.y;
            As[c4 + 2][row] = av.z; As[c4 + 3][row] = av.w;
            float4 wv = *(const float4*)(Wptr + (size_t)row * 1024 + k0 + c4);
            Bs[c4 + 0][row] = wv.x; Bs[c4 + 1][row] = wv.y;
            Bs[c4 + 2][row] = wv.z; Bs[c4 + 3][row] = wv.w;
        }
        __syncthreads();
#pragma unroll
        for (int k = 0; k < 16; k++) {
            float a[8], b[8];
            *(float4*)&a[0] = *(const float4*)&As[k][ty * 8];
            *(float4*)&a[4] = *(const float4*)&As[k][ty * 8 + 4];
            *(float4*)&b[0] = *(const float4*)&Bs[k][tx * 8];
            *(float4*)&b[4] = *(const float4*)&Bs[k][tx * 8 + 4];
#pragma unroll
            for (int u = 0; u < 8; u++)
#pragma unroll
                for (int v = 0; v < 8; v++) acc[u][v] += a[u] * b[v];
        }
        __syncthreads();
    }

#pragma unroll
    for (int u = 0; u < 8; u++) {
        int m = bm * 128 + ty * 8 + u;
        int b = m >> 11;          // / SEQ
        int s = m & (SEQ - 1);
#pragma unroll
        for (int v = 0; v < 8; v++) {
            int n = bn * 128 + tx * 8 + v;
            float val = acc[u][v] + bias[n];
            if (headsplit) {
                int h = n >> 6, dd = n & 63;
                g_Q[0]; // no-op keep
                C[((size_t)((b * NUM_HEADS + h) * SEQ + s) << 6) + dd] = val;
            } else {
                C[(size_t)m * D_MODEL + n] = val;
            }
        }
    }
}

// Flash attention: one CTA per (bh, q-tile of 64). 256 threads, 4x4 microtile.
__global__ __launch_bounds__(256) void attn_kernel()
{
    const int qt = blockIdx.x;   // 0..31
    const int bh = blockIdx.y;   // 0..31  (b*16 + h)
    __shared__ float Qs[64][65];
    __shared__ float Ks[64][65];
    __shared__ float Vs[64][65];
    const int t  = threadIdx.x;
    const int ty = t >> 4, tx = t & 15;
    const float scale = 0.125f;  // 1/sqrt(64)

    const float* Qbase = g_Q + ((size_t)bh * SEQ + qt * 64) * 64;
    const float* Kbase = g_K + (size_t)bh * SEQ * 64;
    const float* Vbase = g_V + (size_t)bh * SEQ * 64;

    for (int idx = t; idx < 64 * 64; idx += 256)
        Qs[idx >> 6][idx & 63] = Qbase[idx] * scale;

    float m_i[4], l_i[4], acc[4][4];
#pragma unroll
    for (int i = 0; i < 4; i++) {
        m_i[i] = -1e30f; l_i[i] = 0.f;
#pragma unroll
        for (int j = 0; j < 4; j++) acc[i][j] = 0.f;
    }
    __syncthreads();

    for (int kt = 0; kt < SEQ / 64; kt++) {
        for (int idx = t; idx < 64 * 64; idx += 256) {
            Ks[idx >> 6][idx & 63] = Kbase[kt * 4096 + idx];
            Vs[idx >> 6][idx & 63] = Vbase[kt * 4096 + idx];
        }
        __syncthreads();

        // scores: s[i][j] for rows ty*4+i, keys tx*4+j
        float s[4][4];
#pragma unroll
        for (int i = 0; i < 4; i++)
#pragma unroll
            for (int j = 0; j < 4; j++) s[i][j] = 0.f;

#pragma unroll 16
        for (int c = 0; c < 64; c++) {
            float a[4], b[4];
#pragma unroll
            for (int i = 0; i < 4; i++) a[i] = Qs[ty * 4 + i][c];
#pragma unroll
            for (int j = 0; j < 4; j++) b[j] = Ks[tx * 4 + j][c];
#pragma unroll
            for (int i = 0; i < 4; i++)
#pragma unroll
                for (int j = 0; j < 4; j++) s[i][j] += a[i] * b[j];
        }

        // online softmax per row (16 threads of same ty own one row-group)
#pragma unroll
        for (int i = 0; i < 4; i++) {
            float tm = fmaxf(fmaxf(s[i][0], s[i][1]), fmaxf(s[i][2], s[i][3]));
#pragma unroll
            for (int o = 1; o < 16; o <<= 1)
                tm = fmaxf(tm, __shfl_xor_sync(0xffffffffu, tm, o, 16));
            float newm = fmaxf(m_i[i], tm);
            float tl = 0.f;
#pragma unroll
            for (int j = 0; j < 4; j++) {
                s[i][j] = __expf(s[i][j] - newm);
                tl += s[i][j];
            }
#pragma unroll
            for (int o = 1; o < 16; o <<= 1)
                tl += __shfl_xor_sync(0xffffffffu, tl, o, 16);
            float alpha = __expf(m_i[i] - newm);
            m_i[i] = newm;
            l_i[i] = l_i[i] * alpha + tl;
#pragma unroll
            for (int j = 0; j < 4; j++) acc[i][j] *= alpha;
        }

        // O += P * V ; P redistributed with shfl (width 16)
#pragma unroll
        for (int kb = 0; kb < 16; kb++) {
#pragma unroll
            for (int kj = 0; kj < 4; kj++) {
                const int kk = kb * 4 + kj;
                float v0 = Vs[kk][tx * 4 + 0];
                float v1 = Vs[kk][tx * 4 + 1];
                float v2 = Vs[kk][tx * 4 + 2];
                float v3 = Vs[kk][tx * 4 + 3];
#pragma unroll
                for (int i = 0; i < 4; i++) {
                    float pv = __shfl_sync(0xffffffffu, s[i][kj], kb, 16);
                    acc[i][0] += pv * v0;
                    acc[i][1] += pv * v1;
                    acc[i][2] += pv * v2;
                    acc[i][3] += pv * v3;
                }
            }
        }
        __syncthreads();
    }

    const int b = bh >> 4, h = bh & 15;
#pragma unroll
    for (int i = 0; i < 4; i++) {
        int r = ty * 4 + i;
        float inv = 1.0f / l_i[i];
        size_t rowbase = ((size_t)(b * SEQ + qt * 64 + r)) * D_MODEL + h * 64;
#pragma unroll
        for (int j = 0; j < 4; j++)
            g_ctx[rowbase + tx * 4 + j] = acc[i][j] * inv;
    }
}

extern "C" void kernel_launch(void* const* d_in, const int* in_sizes, int n_in,
                              void* d_out, int out_size)
{
    const float* query = (const float*)d_in[0];
    const float* key   = (const float*)d_in[1];
    const float* value = (const float*)d_in[2];
    const float* Wq    = (const float*)d_in[3];
    const float* bq    = (const float*)d_in[4];
    const float* Wk    = (const float*)d_in[5];
    const float* bk    = (const float*)d_in[6];
    const float* Wv    = (const float*)d_in[7];
    const float* bv    = (const float*)d_in[8];
    const float* Wo    = (const float*)d_in[9];
    const float* bo    = (const float*)d_in[10];
    float* out = (float*)d_out;

    float* gQ;  cudaGetSymbolAddress((void**)&gQ,  g_Q);
    float* gK;  cudaGetSymbolAddress((void**)&gK,  g_K);
    float* gV;  cudaGetSymbolAddress((void**)&gV,  g_V);
    float* gC;  cudaGetSymbolAddress((void**)&gC,  g_ctx);

    dim3 ggrid(MTOT / 128, D_MODEL / 128);
    gemm_nt_kernel<<<ggrid, 256>>>(query, Wq, bq, gQ, 1);
    gemm_nt_kernel<<<ggrid, 256>>>(key,   Wk, bk, gK, 1);
    gemm_nt_kernel<<<ggrid, 256>>>(value, Wv, bv, gV, 1);

    dim3 agrid(SEQ / 64, BATCH * NUM_HEADS);
    attn_kernel<<<agrid, 256>>>();

    gemm_nt_kernel<<<ggrid, 256>>>(gC, Wo, bo, out, 0);
}

// round 2
// speedup vs baseline: 3.3218x; 3.3218x over previous
#include <cuda_runtime.h>

#define D_MODEL   1024
#define NUM_HEADS 16
#define SEQ       2048
#define BATCH     2
#define MTOT      (BATCH*SEQ)   /* 4096 */

// Scratch (allocation-free rule: __device__ globals).
__device__ float g_Q[(size_t)MTOT * D_MODEL];
__device__ float g_K[(size_t)MTOT * D_MODEL];
__device__ float g_V[(size_t)MTOT * D_MODEL];
__device__ float g_ctx[(size_t)MTOT * D_MODEL];

__device__ __forceinline__ unsigned f2tf(float x) {
    unsigned r; asm("cvt.rna.tf32.f32 %0, %1;" : "=r"(r) : "f"(x)); return r;
}
__device__ __forceinline__ float f2tff(float x) { return __uint_as_float(f2tf(x)); }

__device__ __forceinline__ void ldsm4(unsigned& r0, unsigned& r1, unsigned& r2, unsigned& r3,
                                      const float* p) {
    unsigned a = (unsigned)__cvta_generic_to_shared(p);
    asm volatile("ldmatrix.sync.aligned.m8n8.x4.shared.b16 {%0,%1,%2,%3}, [%4];"
                 : "=r"(r0), "=r"(r1), "=r"(r2), "=r"(r3) : "r"(a));
}
__device__ __forceinline__ void mma8(float* c, unsigned a0, unsigned a1, unsigned a2, unsigned a3,
                                     unsigned b0, unsigned b1) {
    asm volatile("mma.sync.aligned.m16n8k8.row.col.f32.tf32.tf32.f32 "
                 "{%0,%1,%2,%3},{%4,%5,%6,%7},{%8,%9},{%0,%1,%2,%3};"
                 : "+f"(c[0]), "+f"(c[1]), "+f"(c[2]), "+f"(c[3])
                 : "r"(a0), "r"(a1), "r"(a2), "r"(a3), "r"(b0), "r"(b1));
}

// ------------------------- tf32 GEMM: C = A * W^T + bias -------------------------
// A:[MTOT,1024] rm, W:[1024,1024] rm. CTA tile 128x128, k-step 32, 8 warps (32x64 each).
#define GP 36  // smem row pitch in floats (k-dim 32 + pad; keeps LDSM rows conflict-free)

__global__ __launch_bounds__(256, 2) void gemm_tf32(
    const float* __restrict__ A, const float* __restrict__ W,
    const float* __restrict__ bias, float* __restrict__ C, int headsplit)
{
    __shared__ float As[128 * GP];
    __shared__ float Bs[128 * GP];
    const int t = threadIdx.x, lane = t & 31, warp = t >> 5;
    const int wm = warp >> 1, wn = warp & 1;
    const int g = lane >> 2, tt = lane & 3;
    const int bm = blockIdx.x, bn = blockIdx.y;

    float acc[2][8][4];
#pragma unroll
    for (int mt = 0; mt < 2; mt++)
#pragma unroll
        for (int nt = 0; nt < 8; nt++)
#pragma unroll
            for (int i = 0; i < 4; i++) acc[mt][nt][i] = 0.f;

    const float* Ap = A + (size_t)bm * 128 * 1024;
    const float* Wp = W + (size_t)bn * 128 * 1024;

    // ldmatrix lane->address mapping (A-frag and B-frag layouts)
    const int a_row = (lane & 7) + ((lane & 8) ? 8 : 0);
    const int a_col = (lane & 16) ? 4 : 0;
    const int b_row = (lane & 7) + ((lane & 16) ? 8 : 0);
    const int b_col = (lane & 8) ? 4 : 0;

    for (int k0 = 0; k0 < 1024; k0 += 32) {
#pragma unroll
        for (int l = 0; l < 4; l++) {
            int s = t + 256 * l;          // 0..1023 float4 slots
            int m = s >> 3;               // 0..127
            int c4 = (s & 7) << 2;        // 0..28
            float4 av = *(const float4*)(Ap + (size_t)m * 1024 + k0 + c4);
            float4 as; as.x = f2tff(av.x); as.y = f2tff(av.y); as.z = f2tff(av.z); as.w = f2tff(av.w);
            *(float4*)&As[m * GP + c4] = as;
            float4 wv = *(const float4*)(Wp + (size_t)m * 1024 + k0 + c4);
            float4 ws; ws.x = f2tff(wv.x); ws.y = f2tff(wv.y); ws.z = f2tff(wv.z); ws.w = f2tff(wv.w);
            *(float4*)&Bs[m * GP + c4] = ws;
        }
        __syncthreads();
#pragma unroll
        for (int kq = 0; kq < 32; kq += 8) {
            unsigned a[2][4];
#pragma unroll
            for (int mt = 0; mt < 2; mt++) {
                int base = wm * 32 + mt * 16;
                ldsm4(a[mt][0], a[mt][1], a[mt][2], a[mt][3],
                      &As[(base + a_row) * GP + kq + a_col]);
            }
            unsigned b[8][2];
#pragma unroll
            for (int np = 0; np < 4; np++) {
                int nb = wn * 64 + np * 16;
                ldsm4(b[np * 2][0], b[np * 2][1], b[np * 2 + 1][0], b[np * 2 + 1][1],
                      &Bs[(nb + b_row) * GP + kq + b_col]);
            }
#pragma unroll
            for (int mt = 0; mt < 2; mt++)
#pragma unroll
                for (int nt = 0; nt < 8; nt++)
                    mma8(acc[mt][nt], a[mt][0], a[mt][1], a[mt][2], a[mt][3],
                         b[nt][0], b[nt][1]);
        }
        __syncthreads();
    }

#pragma unroll
    for (int mt = 0; mt < 2; mt++) {
        int row0 = bm * 128 + wm * 32 + mt * 16 + g;
#pragma unroll
        for (int nt = 0; nt < 8; nt++) {
            int cc = bn * 128 + wn * 64 + nt * 8 + 2 * tt;
            float2 bb = *(const float2*)&bias[cc];
#pragma unroll
            for (int rp = 0; rp < 2; rp++) {
                int row = row0 + rp * 8;
                float2 v;
                v.x = acc[mt][nt][rp * 2 + 0] + bb.x;
                v.y = acc[mt][nt][rp * 2 + 1] + bb.y;
                if (headsplit) {
                    int b = row >> 11, s = row & (SEQ - 1);
                    int h = cc >> 6, dd = cc & 63;
                    *(float2*)&C[((size_t)((b * NUM_HEADS + h) * SEQ + s) << 6) + dd] = v;
                } else {
                    *(float2*)&C[(size_t)row * D_MODEL + cc] = v;
                }
            }
        }
    }
}

// ------------------------- flash attention, tf32 mma -------------------------
// CTA: 256 threads (8 warps), Br=128 q rows, Bc=64 keys. Warp owns 16 q rows.
#define KP 68  // smem row pitch (d/key dim 64 + pad)

__global__ __launch_bounds__(256, 1) void attn_tf32()
{
    __shared__ float Ks[64 * KP];
    __shared__ float Vs[64 * KP];
    const int t = threadIdx.x, lane = t & 31, warp = t >> 5;
    const int g = lane >> 2, tt = lane & 3;
    const int qt = blockIdx.x;   // 0..15 (q tiles of 128)
    const int bh = blockIdx.y;   // 0..31

    const float* Qb = g_Q + ((size_t)bh * SEQ + qt * 128) * 64;
    const float* Kb = g_K + (size_t)bh * SEQ * 64;
    const float* Vb = g_V + (size_t)bh * SEQ * 64;

    // Q fragments in registers (scale folded): 8 k-steps x 4 regs
    unsigned Qf[8][4];
    const int qr = warp * 16;
#pragma unroll
    for (int dq = 0; dq < 8; dq++) {
        Qf[dq][0] = f2tf(0.125f * Qb[(qr + g)     * 64 + dq * 8 + tt]);
        Qf[dq][1] = f2tf(0.125f * Qb[(qr + g + 8) * 64 + dq * 8 + tt]);
        Qf[dq][2] = f2tf(0.125f * Qb[(qr + g)     * 64 + dq * 8 + tt + 4]);
        Qf[dq][3] = f2tf(0.125f * Qb[(qr + g + 8) * 64 + dq * 8 + tt + 4]);
    }

    float Of[8][4];
#pragma unroll
    for (int nt = 0; nt < 8; nt++)
#pragma unroll
        for (int i = 0; i < 4; i++) Of[nt][i] = 0.f;
    float mrow[2] = {-1e30f, -1e30f};
    float lrow[2] = {0.f, 0.f};

    const int b_row = (lane & 7) + ((lane & 16) ? 8 : 0);
    const int b_col = (lane & 8) ? 4 : 0;

    for (int kt = 0; kt < SEQ / 64; kt++) {
#pragma unroll
        for (int l = 0; l < 4; l++) {
            int s = t + 256 * l;          // 0..1023
            int r = s >> 4;               // key row 0..63
            int c4 = (s & 15) << 2;       // 0..60
            float4 kv = *(const float4*)(Kb + (size_t)(kt * 64 + r) * 64 + c4);
            float4 ks; ks.x = f2tff(kv.x); ks.y = f2tff(kv.y); ks.z = f2tff(kv.z); ks.w = f2tff(kv.w);
            *(float4*)&Ks[r * KP + c4] = ks;
            float4 vv = *(const float4*)(Vb + (size_t)(kt * 64 + r) * 64 + c4);
            float4 vs; vs.x = f2tff(vv.x); vs.y = f2tff(vv.y); vs.z = f2tff(vv.z); vs.w = f2tff(vv.w);
            *(float4*)&Vs[r * KP + c4] = vs;
        }
        __syncthreads();

        // S = Q K^T  (k-dim = d, 8 steps)
        float sf[8][4];
#pragma unroll
        for (int nt = 0; nt < 8; nt++)
#pragma unroll
            for (int i = 0; i < 4; i++) sf[nt][i] = 0.f;

#pragma unroll
        for (int dq = 0; dq < 8; dq++) {
            unsigned b[8][2];
#pragma unroll
            for (int np = 0; np < 4; np++)
                ldsm4(b[np * 2][0], b[np * 2][1], b[np * 2 + 1][0], b[np * 2 + 1][1],
                      &Ks[(np * 16 + b_row) * KP + dq * 8 + b_col]);
#pragma unroll
            for (int nt = 0; nt < 8; nt++)
                mma8(sf[nt], Qf[dq][0], Qf[dq][1], Qf[dq][2], Qf[dq][3],
                     b[nt][0], b[nt][1]);
        }

        // online softmax (rows g and g+8; cols spread over tt-group of 4 lanes)
        float alpha[2];
#pragma unroll
        for (int rp = 0; rp < 2; rp++) {
            float mx = -1e30f;
#pragma unroll
            for (int nt = 0; nt < 8; nt++)
                mx = fmaxf(mx, fmaxf(sf[nt][rp * 2], sf[nt][rp * 2 + 1]));
            mx = fmaxf(mx, __shfl_xor_sync(0xffffffffu, mx, 1));
            mx = fmaxf(mx, __shfl_xor_sync(0xffffffffu, mx, 2));
            float nm = fmaxf(mrow[rp], mx);
            float sum = 0.f;
#pragma unroll
            for (int nt = 0; nt < 8; nt++) {
                float p0 = __expf(sf[nt][rp * 2] - nm);
                float p1 = __expf(sf[nt][rp * 2 + 1] - nm);
                sf[nt][rp * 2] = p0; sf[nt][rp * 2 + 1] = p1;
                sum += p0 + p1;
            }
            sum += __shfl_xor_sync(0xffffffffu, sum, 1);
            sum += __shfl_xor_sync(0xffffffffu, sum, 2);
            alpha[rp] = __expf(mrow[rp] - nm);
            mrow[rp] = nm;
            lrow[rp] = lrow[rp] * alpha[rp] + sum;
        }
#pragma unroll
        for (int nt = 0; nt < 8; nt++) {
            Of[nt][0] *= alpha[0]; Of[nt][1] *= alpha[0];
            Of[nt][2] *= alpha[1]; Of[nt][3] *= alpha[1];
        }
        // P -> tf32 in place
#pragma unroll
        for (int nt = 0; nt < 8; nt++)
#pragma unroll
            for (int i = 0; i < 4; i++) sf[nt][i] = __uint_as_float(f2tf(sf[nt][i]));

        // O += P V  (k-dim = key, 8 steps; P relayout C-frag -> A-frag via shfl)
        const unsigned* Vsu = (const unsigned*)Vs;
        const int src  = (g << 2) | (tt >> 1);
        const int src2 = src + 2;
#pragma unroll
        for (int kq = 0; kq < 8; kq++) {
            unsigned e0 = __float_as_uint(__shfl_sync(0xffffffffu, sf[kq][0], src));
            unsigned o0 = __float_as_uint(__shfl_sync(0xffffffffu, sf[kq][1], src));
            unsigned e1 = __float_as_uint(__shfl_sync(0xffffffffu, sf[kq][2], src));
            unsigned o1 = __float_as_uint(__shfl_sync(0xffffffffu, sf[kq][3], src));
            unsigned e2 = __float_as_uint(__shfl_sync(0xffffffffu, sf[kq][0], src2));
            unsigned o2 = __float_as_uint(__shfl_sync(0xffffffffu, sf[kq][1], src2));
            unsigned e3 = __float_as_uint(__shfl_sync(0xffffffffu, sf[kq][2], src2));
            unsigned o3 = __float_as_uint(__shfl_sync(0xffffffffu, sf[kq][3], src2));
            unsigned a0 = (tt & 1) ? o0 : e0;
            unsigned a1 = (tt & 1) ? o1 : e1;
            unsigned a2 = (tt & 1) ? o2 : e2;
            unsigned a3 = (tt & 1) ? o3 : e3;
#pragma unroll
            for (int nt = 0; nt < 8; nt++) {
                unsigned b0 = Vsu[(kq * 8 + tt)     * KP + nt * 8 + g];
                unsigned b1 = Vsu[(kq * 8 + tt + 4) * KP + nt * 8 + g];
                mma8(Of[nt], a0, a1, a2, a3, b0, b1);
            }
        }
        __syncthreads();
    }

    const int b = bh >> 4, h = bh & 15;
    const float inv0 = 1.f / lrow[0], inv1 = 1.f / lrow[1];
    const int row = qt * 128 + warp * 16 + g;
#pragma unroll
    for (int nt = 0; nt < 8; nt++) {
        size_t base  = ((size_t)(b * SEQ + row))     * D_MODEL + h * 64 + nt * 8 + 2 * tt;
        size_t base2 = ((size_t)(b * SEQ + row + 8)) * D_MODEL + h * 64 + nt * 8 + 2 * tt;
        float2 v0; v0.x = Of[nt][0] * inv0; v0.y = Of[nt][1] * inv0;
        float2 v1; v1.x = Of[nt][2] * inv1; v1.y = Of[nt][3] * inv1;
        *(float2*)&g_ctx[base]  = v0;
        *(float2*)&g_ctx[base2] = v1;
    }
}

extern "C" void kernel_launch(void* const* d_in, const int* in_sizes, int n_in,
                              void* d_out, int out_size)
{
    const float* query = (const float*)d_in[0];
    const float* key   = (const float*)d_in[1];
    const float* value = (const float*)d_in[2];
    const float* Wq    = (const float*)d_in[3];
    const float* bq    = (const float*)d_in[4];
    const float* Wk    = (const float*)d_in[5];
    const float* bk    = (const float*)d_in[6];
    const float* Wv    = (const float*)d_in[7];
    const float* bv    = (const float*)d_in[8];
    const float* Wo    = (const float*)d_in[9];
    const float* bo    = (const float*)d_in[10];
    float* out = (float*)d_out;

    float* gQ;  cudaGetSymbolAddress((void**)&gQ,  g_Q);
    float* gK;  cudaGetSymbolAddress((void**)&gK,  g_K);
    float* gV;  cudaGetSymbolAddress((void**)&gV,  g_V);
    float* gC;  cudaGetSymbolAddress((void**)&gC,  g_ctx);

    dim3 ggrid(MTOT / 128, D_MODEL / 128);
    gemm_tf32<<<ggrid, 256>>>(query, Wq, bq, gQ, 1);
    gemm_tf32<<<ggrid, 256>>>(key,   Wk, bk, gK, 1);
    gemm_tf32<<<ggrid, 256>>>(value, Wv, bv, gV, 1);

    dim3 agrid(SEQ / 128, BATCH * NUM_HEADS);
    attn_tf32<<<agrid, 256>>>();

    gemm_tf32<<<ggrid, 256>>>(gC, Wo, bo, out, 0);
}

// round 3
// speedup vs baseline: 3.6664x; 1.1037x over previous
#include <cuda_runtime.h>

#define D_MODEL   1024
#define NUM_HEADS 16
#define SEQ       2048
#define BATCH     2
#define MTOT      (BATCH*SEQ)   /* 4096 */
#define LOG2E     1.4426950408889634f

// Scratch (allocation-free rule: __device__ globals).
__device__ float g_Q[(size_t)MTOT * D_MODEL];
__device__ float g_K[(size_t)MTOT * D_MODEL];
__device__ float g_V[(size_t)MTOT * D_MODEL];   // stored TRANSPOSED: [b,h,d,seq]
__device__ float g_ctx[(size_t)MTOT * D_MODEL];

__device__ __forceinline__ unsigned f2tf(float x) {
    unsigned r; asm("cvt.rna.tf32.f32 %0, %1;" : "=r"(r) : "f"(x)); return r;
}
__device__ __forceinline__ float f2tff(float x) { return __uint_as_float(f2tf(x)); }

__device__ __forceinline__ void ldsm4(unsigned& r0, unsigned& r1, unsigned& r2, unsigned& r3,
                                      const float* p) {
    unsigned a = (unsigned)__cvta_generic_to_shared(p);
    asm volatile("ldmatrix.sync.aligned.m8n8.x4.shared.b16 {%0,%1,%2,%3}, [%4];"
                 : "=r"(r0), "=r"(r1), "=r"(r2), "=r"(r3) : "r"(a));
}
__device__ __forceinline__ void mma8(float* c, unsigned a0, unsigned a1, unsigned a2, unsigned a3,
                                     unsigned b0, unsigned b1) {
    asm volatile("mma.sync.aligned.m16n8k8.row.col.f32.tf32.tf32.f32 "
                 "{%0,%1,%2,%3},{%4,%5,%6,%7},{%8,%9},{%0,%1,%2,%3};"
                 : "+f"(c[0]), "+f"(c[1]), "+f"(c[2]), "+f"(c[3])
                 : "r"(a0), "r"(a1), "r"(a2), "r"(a3), "r"(b0), "r"(b1));
}

// ------------------------- tf32 GEMM: C = A * W^T + bias -------------------------
// mode 0: plain [m,n]; mode 1: headsplit [b,h,s,d]; mode 2: headsplit TRANSPOSED [b,h,d,s]
#define GP 36

__global__ __launch_bounds__(256, 2) void gemm_tf32(
    const float* __restrict__ A, const float* __restrict__ W,
    const float* __restrict__ bias, float* __restrict__ C, int mode)
{
    __shared__ float As[128 * GP];
    __shared__ float Bs[128 * GP];
    const int t = threadIdx.x, lane = t & 31, warp = t >> 5;
    const int wm = warp >> 1, wn = warp & 1;
    const int g = lane >> 2, tt = lane & 3;
    const int bm = blockIdx.x, bn = blockIdx.y;

    float acc[2][8][4];
#pragma unroll
    for (int mt = 0; mt < 2; mt++)
#pragma unroll
        for (int nt = 0; nt < 8; nt++)
#pragma unroll
            for (int i = 0; i < 4; i++) acc[mt][nt][i] = 0.f;

    const float* Ap = A + (size_t)bm * 128 * 1024;
    const float* Wp = W + (size_t)bn * 128 * 1024;

    const int a_row = (lane & 7) + ((lane & 8) ? 8 : 0);
    const int a_col = (lane & 16) ? 4 : 0;
    const int b_row = (lane & 7) + ((lane & 16) ? 8 : 0);
    const int b_col = (lane & 8) ? 4 : 0;

    for (int k0 = 0; k0 < 1024; k0 += 32) {
#pragma unroll
        for (int l = 0; l < 4; l++) {
            int s = t + 256 * l;
            int m = s >> 3;
            int c4 = (s & 7) << 2;
            float4 av = *(const float4*)(Ap + (size_t)m * 1024 + k0 + c4);
            float4 as; as.x = f2tff(av.x); as.y = f2tff(av.y); as.z = f2tff(av.z); as.w = f2tff(av.w);
            *(float4*)&As[m * GP + c4] = as;
            float4 wv = *(const float4*)(Wp + (size_t)m * 1024 + k0 + c4);
            float4 ws; ws.x = f2tff(wv.x); ws.y = f2tff(wv.y); ws.z = f2tff(wv.z); ws.w = f2tff(wv.w);
            *(float4*)&Bs[m * GP + c4] = ws;
        }
        __syncthreads();
#pragma unroll
        for (int kq = 0; kq < 32; kq += 8) {
            unsigned a[2][4];
#pragma unroll
            for (int mt = 0; mt < 2; mt++) {
                int base = wm * 32 + mt * 16;
                ldsm4(a[mt][0], a[mt][1], a[mt][2], a[mt][3],
                      &As[(base + a_row) * GP + kq + a_col]);
            }
            unsigned b[8][2];
#pragma unroll
            for (int np = 0; np < 4; np++) {
                int nb = wn * 64 + np * 16;
                ldsm4(b[np * 2][0], b[np * 2][1], b[np * 2 + 1][0], b[np * 2 + 1][1],
                      &Bs[(nb + b_row) * GP + kq + b_col]);
            }
#pragma unroll
            for (int mt = 0; mt < 2; mt++)
#pragma unroll
                for (int nt = 0; nt < 8; nt++)
                    mma8(acc[mt][nt], a[mt][0], a[mt][1], a[mt][2], a[mt][3],
                         b[nt][0], b[nt][1]);
        }
        __syncthreads();
    }

#pragma unroll
    for (int mt = 0; mt < 2; mt++) {
        int row0 = bm * 128 + wm * 32 + mt * 16 + g;
#pragma unroll
        for (int nt = 0; nt < 8; nt++) {
            int cc = bn * 128 + wn * 64 + nt * 8 + 2 * tt;
            float2 bb = *(const float2*)&bias[cc];
#pragma unroll
            for (int rp = 0; rp < 2; rp++) {
                int row = row0 + rp * 8;
                float2 v;
                v.x = acc[mt][nt][rp * 2 + 0] + bb.x;
                v.y = acc[mt][nt][rp * 2 + 1] + bb.y;
                int b = row >> 11, sq = row & (SEQ - 1);
                int h = cc >> 6, dd = cc & 63;
                if (mode == 1) {
                    *(float2*)&C[((size_t)((b * NUM_HEADS + h) * SEQ + sq) << 6) + dd] = v;
                } else if (mode == 2) {
                    size_t base = (size_t)((b * NUM_HEADS + h) * 64 + dd) * SEQ + sq;
                    C[base] = v.x;
                    C[base + SEQ] = v.y;   // dd+1 row
                } else {
                    *(float2*)&C[(size_t)row * D_MODEL + cc] = v;
                }
            }
        }
    }
}

// ------------------------- flash attention, tf32 mma -------------------------
// CTA: 8 warps, Br=128 q rows; smem tiles of 128 keys (double buffered),
// softmax processed in two 64-key halves. V^T in smem -> ldmatrix B-frags for PV.
#define KP  68    /* K smem pitch (d=64 + 4)       */
#define VP  132   /* V^T smem pitch (keys=128 + 4) */
#define KS_STRIDE (128 * KP)   /* 8704 floats */
#define VT_STRIDE (64 * VP)    /* 8448 floats */
#define ATTN_SMEM_BYTES ((2 * KS_STRIDE + 2 * VT_STRIDE) * 4)  /* 137216 */

__global__ __launch_bounds__(256, 1) void attn_tf32()
{
    extern __shared__ float sm[];
    float* const Ksm0 = sm;
    float* const Ksm1 = sm + KS_STRIDE;
    float* const Vsm0 = sm + 2 * KS_STRIDE;
    float* const Vsm1 = sm + 2 * KS_STRIDE + VT_STRIDE;

    const int t = threadIdx.x, lane = t & 31, warp = t >> 5;
    const int g = lane >> 2, tt = lane & 3;
    const int qt = blockIdx.x;   // 0..15
    const int bh = blockIdx.y;   // 0..31

    const float* Qb  = g_Q + ((size_t)bh * SEQ + qt * 128) * 64;
    const float* Kb  = g_K + (size_t)bh * SEQ * 64;
    const float* Vtb = g_V + (size_t)bh * 64 * SEQ;   // [d][seq]

    // Q fragments (scale 1/8 and log2e folded in)
    unsigned Qf[8][4];
    const int qr = warp * 16;
    const float qs = 0.125f * LOG2E;
#pragma unroll
    for (int dq = 0; dq < 8; dq++) {
        Qf[dq][0] = f2tf(qs * Qb[(qr + g)     * 64 + dq * 8 + tt]);
        Qf[dq][1] = f2tf(qs * Qb[(qr + g + 8) * 64 + dq * 8 + tt]);
        Qf[dq][2] = f2tf(qs * Qb[(qr + g)     * 64 + dq * 8 + tt + 4]);
        Qf[dq][3] = f2tf(qs * Qb[(qr + g + 8) * 64 + dq * 8 + tt + 4]);
    }

    float Of[8][4];
#pragma unroll
    for (int nt = 0; nt < 8; nt++)
#pragma unroll
        for (int i = 0; i < 4; i++) Of[nt][i] = 0.f;
    float mrow[2] = {-1e30f, -1e30f};
    float lrow[2] = {0.f, 0.f};

    const int b_row = (lane & 7) + ((lane & 16) ? 8 : 0);
    const int b_col = (lane & 8) ? 4 : 0;

    // ---- prologue: load tile 0 into regs, store to buffer 0 ----
    float4 kreg[8], vreg[8];
#pragma unroll
    for (int l = 0; l < 8; l++) {
        int s = t + 256 * l;
        kreg[l] = *(const float4*)(Kb + (size_t)(s >> 4) * 64 + ((s & 15) << 2));
        vreg[l] = *(const float4*)(Vtb + (size_t)(s >> 5) * SEQ + ((s & 31) << 2));
    }
#pragma unroll
    for (int l = 0; l < 8; l++) {
        int s = t + 256 * l;
        float4 kv = kreg[l];
        float4 ks; ks.x = f2tff(kv.x); ks.y = f2tff(kv.y); ks.z = f2tff(kv.z); ks.w = f2tff(kv.w);
        *(float4*)&Ksm0[(s >> 4) * KP + ((s & 15) << 2)] = ks;
        float4 vv = vreg[l];
        float4 vs; vs.x = f2tff(vv.x); vs.y = f2tff(vv.y); vs.z = f2tff(vv.z); vs.w = f2tff(vv.w);
        *(float4*)&Vsm0[(s >> 5) * VP + ((s & 31) << 2)] = vs;
    }
    __syncthreads();

    const int src  = (g << 2) | (tt >> 1);
    const int src2 = src + 2;

    for (int kt = 0; kt < SEQ / 128; kt++) {
        float* const Kcur = (kt & 1) ? Ksm1 : Ksm0;
        float* const Vcur = (kt & 1) ? Vsm1 : Vsm0;
        float* const Knxt = (kt & 1) ? Ksm0 : Ksm1;
        float* const Vnxt = (kt & 1) ? Vsm0 : Vsm1;

        // prefetch next tile into registers (latency hidden behind compute)
        if (kt < SEQ / 128 - 1) {
            const float* Kp = Kb + (size_t)(kt + 1) * 128 * 64;
            const float* Vp = Vtb + (kt + 1) * 128;
#pragma unroll
            for (int l = 0; l < 8; l++) {
                int s = t + 256 * l;
                kreg[l] = *(const float4*)(Kp + (size_t)(s >> 4) * 64 + ((s & 15) << 2));
                vreg[l] = *(const float4*)(Vp + (size_t)(s >> 5) * SEQ + ((s & 31) << 2));
            }
        }

#pragma unroll
        for (int hf = 0; hf < 2; hf++) {
            const int hk = hf * 64;

            // ---- S = Q K^T over this 64-key half ----
            float sf[8][4];
#pragma unroll
            for (int nt = 0; nt < 8; nt++)
#pragma unroll
                for (int i = 0; i < 4; i++) sf[nt][i] = 0.f;

#pragma unroll
            for (int dq = 0; dq < 8; dq++) {
                unsigned b[8][2];
#pragma unroll
                for (int np = 0; np < 4; np++)
                    ldsm4(b[np * 2][0], b[np * 2][1], b[np * 2 + 1][0], b[np * 2 + 1][1],
                          &Kcur[(hk + np * 16 + b_row) * KP + dq * 8 + b_col]);
#pragma unroll
                for (int nt = 0; nt < 8; nt++)
                    mma8(sf[nt], Qf[dq][0], Qf[dq][1], Qf[dq][2], Qf[dq][3],
                         b[nt][0], b[nt][1]);
            }

            // ---- online softmax in exp2 domain ----
            float alpha[2];
#pragma unroll
            for (int rp = 0; rp < 2; rp++) {
                float mx = -1e30f;
#pragma unroll
                for (int nt = 0; nt < 8; nt++)
                    mx = fmaxf(mx, fmaxf(sf[nt][rp * 2], sf[nt][rp * 2 + 1]));
                mx = fmaxf(mx, __shfl_xor_sync(0xffffffffu, mx, 1));
                mx = fmaxf(mx, __shfl_xor_sync(0xffffffffu, mx, 2));
                float nm = fmaxf(mrow[rp], mx);
                float sum = 0.f;
#pragma unroll
                for (int nt = 0; nt < 8; nt++) {
                    float p0 = exp2f(sf[nt][rp * 2]     - nm);
                    float p1 = exp2f(sf[nt][rp * 2 + 1] - nm);
                    sf[nt][rp * 2] = p0; sf[nt][rp * 2 + 1] = p1;
                    sum += p0 + p1;
                }
                sum += __shfl_xor_sync(0xffffffffu, sum, 1);
                sum += __shfl_xor_sync(0xffffffffu, sum, 2);
                alpha[rp] = exp2f(mrow[rp] - nm);
                mrow[rp] = nm;
                lrow[rp] = lrow[rp] * alpha[rp] + sum;
            }
#pragma unroll
            for (int nt = 0; nt < 8; nt++) {
                Of[nt][0] *= alpha[0]; Of[nt][1] *= alpha[0];
                Of[nt][2] *= alpha[1]; Of[nt][3] *= alpha[1];
            }
#pragma unroll
            for (int nt = 0; nt < 8; nt++)
#pragma unroll
                for (int i = 0; i < 4; i++) sf[nt][i] = __uint_as_float(f2tf(sf[nt][i]));

            // ---- O += P V  (V^T B-frags via ldmatrix; P relayout via shfl) ----
#pragma unroll
            for (int kq = 0; kq < 8; kq++) {
                unsigned e0 = __float_as_uint(__shfl_sync(0xffffffffu, sf[kq][0], src));
                unsigned o0 = __float_as_uint(__shfl_sync(0xffffffffu, sf[kq][1], src));
                unsigned e1 = __float_as_uint(__shfl_sync(0xffffffffu, sf[kq][2], src));
                unsigned o1 = __float_as_uint(__shfl_sync(0xffffffffu, sf[kq][3], src));
                unsigned e2 = __float_as_uint(__shfl_sync(0xffffffffu, sf[kq][0], src2));
                unsigned o2 = __float_as_uint(__shfl_sync(0xffffffffu, sf[kq][1], src2));
                unsigned e3 = __float_as_uint(__shfl_sync(0xffffffffu, sf[kq][2], src2));
                unsigned o3 = __float_as_uint(__shfl_sync(0xffffffffu, sf[kq][3], src2));
                unsigned a0 = (tt & 1) ? o0 : e0;
                unsigned a1 = (tt & 1) ? o1 : e1;
                unsigned a2 = (tt & 1) ? o2 : e2;
                unsigned a3 = (tt & 1) ? o3 : e3;
                unsigned vb[8][2];
#pragma unroll
                for (int np = 0; np < 4; np++)
                    ldsm4(vb[np * 2][0], vb[np * 2][1], vb[np * 2 + 1][0], vb[np * 2 + 1][1],
                          &Vcur[(np * 16 + b_row) * VP + hk + kq * 8 + b_col]);
#pragma unroll
                for (int nt = 0; nt < 8; nt++)
                    mma8(Of[nt], a0, a1, a2, a3, vb[nt][0], vb[nt][1]);
            }
        }

        // write prefetched tile into the other buffer
        if (kt < SEQ / 128 - 1) {
#pragma unroll
            for (int l = 0; l < 8; l++) {
                int s = t + 256 * l;
                float4 kv = kreg[l];
                float4 ks; ks.x = f2tff(kv.x); ks.y = f2tff(kv.y); ks.z = f2tff(kv.z); ks.w = f2tff(kv.w);
                *(float4*)&Knxt[(s >> 4) * KP + ((s & 15) << 2)] = ks;
                float4 vv = vreg[l];
                float4 vs; vs.x = f2tff(vv.x); vs.y = f2tff(vv.y); vs.z = f2tff(vv.z); vs.w = f2tff(vv.w);
                *(float4*)&Vnxt[(s >> 5) * VP + ((s & 31) << 2)] = vs;
            }
        }
        __syncthreads();
    }

    const int b = bh >> 4, h = bh & 15;
    const float inv0 = 1.f / lrow[0], inv1 = 1.f / lrow[1];
    const int row = qt * 128 + warp * 16 + g;
#pragma unroll
    for (int nt = 0; nt < 8; nt++) {
        size_t base  = ((size_t)(b * SEQ + row))     * D_MODEL + h * 64 + nt * 8 + 2 * tt;
        size_t base2 = ((size_t)(b * SEQ + row + 8)) * D_MODEL + h * 64 + nt * 8 + 2 * tt;
        float2 v0; v0.x = Of[nt][0] * inv0; v0.y = Of[nt][1] * inv0;
        float2 v1; v1.x = Of[nt][2] * inv1; v1.y = Of[nt][3] * inv1;
        *(float2*)&g_ctx[base]  = v0;
        *(float2*)&g_ctx[base2] = v1;
    }
}

extern "C" void kernel_launch(void* const* d_in, const int* in_sizes, int n_in,
                              void* d_out, int out_size)
{
    const float* query = (const float*)d_in[0];
    const float* key   = (const float*)d_in[1];
    const float* value = (const float*)d_in[2];
    const float* Wq    = (const float*)d_in[3];
    const float* bq    = (const float*)d_in[4];
    const float* Wk    = (const float*)d_in[5];
    const float* bk    = (const float*)d_in[6];
    const float* Wv    = (const float*)d_in[7];
    const float* bv    = (const float*)d_in[8];
    const float* Wo    = (const float*)d_in[9];
    const float* bo    = (const float*)d_in[10];
    float* out = (float*)d_out;

    float* gQ;  cudaGetSymbolAddress((void**)&gQ,  g_Q);
    float* gK;  cudaGetSymbolAddress((void**)&gK,  g_K);
    float* gV;  cudaGetSymbolAddress((void**)&gV,  g_V);
    float* gC;  cudaGetSymbolAddress((void**)&gC,  g_ctx);

    cudaFuncSetAttribute(attn_tf32, cudaFuncAttributeMaxDynamicSharedMemorySize,
                         ATTN_SMEM_BYTES);

    dim3 ggrid(MTOT / 128, D_MODEL / 128);
    gemm_tf32<<<ggrid, 256>>>(query, Wq, bq, gQ, 1);
    gemm_tf32<<<ggrid, 256>>>(key,   Wk, bk, gK, 1);
    gemm_tf32<<<ggrid, 256>>>(value, Wv, bv, gV, 2);

    dim3 agrid(SEQ / 128, BATCH * NUM_HEADS);
    attn_tf32<<<agrid, 256, ATTN_SMEM_BYTES>>>();

    gemm_tf32<<<ggrid, 256>>>(gC, Wo, bo, out, 0);
}

// round 4
// speedup vs baseline: 3.7405x; 1.0202x over previous
#include <cuda_runtime.h>

#define D_MODEL   1024
#define NUM_HEADS 16
#define SEQ       2048
#define BATCH     2
#define MTOT      (BATCH*SEQ)   /* 4096 */
#define LOG2E     1.4426950408889634f

// Scratch (allocation-free rule: __device__ globals).
__device__ float g_Q[(size_t)MTOT * D_MODEL];   // [b,h,s,d], tf32-rounded
__device__ float g_K[(size_t)MTOT * D_MODEL];   // [b,h,s,d], tf32-rounded
__device__ float g_V[(size_t)MTOT * D_MODEL];   // TRANSPOSED [b,h,d,s], tf32-rounded
__device__ float g_ctx[(size_t)MTOT * D_MODEL];

__device__ __forceinline__ unsigned f2tf(float x) {
    unsigned r; asm("cvt.rna.tf32.f32 %0, %1;" : "=r"(r) : "f"(x)); return r;
}
__device__ __forceinline__ float f2tff(float x) { return __uint_as_float(f2tf(x)); }

__device__ __forceinline__ void ldsm4(unsigned& r0, unsigned& r1, unsigned& r2, unsigned& r3,
                                      const float* p) {
    unsigned a = (unsigned)__cvta_generic_to_shared(p);
    asm volatile("ldmatrix.sync.aligned.m8n8.x4.shared.b16 {%0,%1,%2,%3}, [%4];"
                 : "=r"(r0), "=r"(r1), "=r"(r2), "=r"(r3) : "r"(a));
}
__device__ __forceinline__ void mma8(float* c, unsigned a0, unsigned a1, unsigned a2, unsigned a3,
                                     unsigned b0, unsigned b1) {
    asm volatile("mma.sync.aligned.m16n8k8.row.col.f32.tf32.tf32.f32 "
                 "{%0,%1,%2,%3},{%4,%5,%6,%7},{%8,%9},{%0,%1,%2,%3};"
                 : "+f"(c[0]), "+f"(c[1]), "+f"(c[2]), "+f"(c[3])
                 : "r"(a0), "r"(a1), "r"(a2), "r"(a3), "r"(b0), "r"(b1));
}
__device__ __forceinline__ void cp16(float* smem_dst, const float* gsrc) {
    unsigned d = (unsigned)__cvta_generic_to_shared(smem_dst);
    asm volatile("cp.async.cg.shared.global [%0], [%1], 16;\n" :: "r"(d), "l"(gsrc));
}
__device__ __forceinline__ void cp_commit() { asm volatile("cp.async.commit_group;\n"); }
template <int N> __device__ __forceinline__ void cp_wait() {
    asm volatile("cp.async.wait_group %0;\n" :: "n"(N));
}

// ------------------------- tf32 GEMM: C = A * W^T + bias -------------------------
// mode 0: plain [m,n] fp32; mode 1: headsplit [b,h,s,d] tf32-rounded;
// mode 2: headsplit TRANSPOSED [b,h,d,s] tf32-rounded
#define GP 36

__global__ __launch_bounds__(256, 2) void gemm_tf32(
    const float* __restrict__ A, const float* __restrict__ W,
    const float* __restrict__ bias, float* __restrict__ C, int mode)
{
    __shared__ float As[128 * GP];
    __shared__ float Bs[128 * GP];
    const int t = threadIdx.x, lane = t & 31, warp = t >> 5;
    const int wm = warp >> 1, wn = warp & 1;
    const int g = lane >> 2, tt = lane & 3;
    const int bm = blockIdx.x, bn = blockIdx.y;

    float acc[2][8][4];
#pragma unroll
    for (int mt = 0; mt < 2; mt++)
#pragma unroll
        for (int nt = 0; nt < 8; nt++)
#pragma unroll
            for (int i = 0; i < 4; i++) acc[mt][nt][i] = 0.f;

    const float* Ap = A + (size_t)bm * 128 * 1024;
    const float* Wp = W + (size_t)bn * 128 * 1024;

    const int a_row = (lane & 7) + ((lane & 8) ? 8 : 0);
    const int a_col = (lane & 16) ? 4 : 0;
    const int b_row = (lane & 7) + ((lane & 16) ? 8 : 0);
    const int b_col = (lane & 8) ? 4 : 0;

    for (int k0 = 0; k0 < 1024; k0 += 32) {
#pragma unroll
        for (int l = 0; l < 4; l++) {
            int s = t + 256 * l;
            int m = s >> 3;
            int c4 = (s & 7) << 2;
            float4 av = *(const float4*)(Ap + (size_t)m * 1024 + k0 + c4);
            float4 as; as.x = f2tff(av.x); as.y = f2tff(av.y); as.z = f2tff(av.z); as.w = f2tff(av.w);
            *(float4*)&As[m * GP + c4] = as;
            float4 wv = *(const float4*)(Wp + (size_t)m * 1024 + k0 + c4);
            float4 ws; ws.x = f2tff(wv.x); ws.y = f2tff(wv.y); ws.z = f2tff(wv.z); ws.w = f2tff(wv.w);
            *(float4*)&Bs[m * GP + c4] = ws;
        }
        __syncthreads();
#pragma unroll
        for (int kq = 0; kq < 32; kq += 8) {
            unsigned a[2][4];
#pragma unroll
            for (int mt = 0; mt < 2; mt++) {
                int base = wm * 32 + mt * 16;
                ldsm4(a[mt][0], a[mt][1], a[mt][2], a[mt][3],
                      &As[(base + a_row) * GP + kq + a_col]);
            }
            unsigned b[8][2];
#pragma unroll
            for (int np = 0; np < 4; np++) {
                int nb = wn * 64 + np * 16;
                ldsm4(b[np * 2][0], b[np * 2][1], b[np * 2 + 1][0], b[np * 2 + 1][1],
                      &Bs[(nb + b_row) * GP + kq + b_col]);
            }
#pragma unroll
            for (int mt = 0; mt < 2; mt++)
#pragma unroll
                for (int nt = 0; nt < 8; nt++)
                    mma8(acc[mt][nt], a[mt][0], a[mt][1], a[mt][2], a[mt][3],
                         b[nt][0], b[nt][1]);
        }
        __syncthreads();
    }

#pragma unroll
    for (int mt = 0; mt < 2; mt++) {
        int row0 = bm * 128 + wm * 32 + mt * 16 + g;
#pragma unroll
        for (int nt = 0; nt < 8; nt++) {
            int cc = bn * 128 + wn * 64 + nt * 8 + 2 * tt;
            float2 bb = *(const float2*)&bias[cc];
#pragma unroll
            for (int rp = 0; rp < 2; rp++) {
                int row = row0 + rp * 8;
                float2 v;
                v.x = acc[mt][nt][rp * 2 + 0] + bb.x;
                v.y = acc[mt][nt][rp * 2 + 1] + bb.y;
                int b = row >> 11, sq = row & (SEQ - 1);
                int h = cc >> 6, dd = cc & 63;
                if (mode == 1) {
                    v.x = f2tff(v.x); v.y = f2tff(v.y);
                    *(float2*)&C[((size_t)((b * NUM_HEADS + h) * SEQ + sq) << 6) + dd] = v;
                } else if (mode == 2) {
                    size_t base = (size_t)((b * NUM_HEADS + h) * 64 + dd) * SEQ + sq;
                    C[base] = f2tff(v.x);
                    C[base + SEQ] = f2tff(v.y);
                } else {
                    *(float2*)&C[(size_t)row * D_MODEL + cc] = v;
                }
            }
        }
    }
}

// ------------------------- flash attention, tf32 mma -------------------------
// 8 warps, Br=128, key tiles of 128 double-buffered via cp.async.
// PV via per-warp smem P staging + ldmatrix (no shfl relayout).
#define KP  68    /* K smem pitch (d=64 + 4)       */
#define VP  132   /* V^T smem pitch (keys=128 + 4) */
#define PP  68    /* P staging pitch (64 + 4)      */
#define KS_STRIDE (128 * KP)   /* 8704 floats  */
#define VT_STRIDE (64 * VP)    /* 8448 floats  */
#define P_STRIDE  (16 * PP)    /* 1088 floats  */
#define ATTN_SMEM_FLOATS (2 * KS_STRIDE + 2 * VT_STRIDE + 8 * P_STRIDE)
#define ATTN_SMEM_BYTES  (ATTN_SMEM_FLOATS * 4)   /* 172032 */

__global__ __launch_bounds__(256, 1) void attn_tf32()
{
    extern __shared__ float sm[];
    float* const Ksm0 = sm;
    float* const Ksm1 = sm + KS_STRIDE;
    float* const Vsm0 = sm + 2 * KS_STRIDE;
    float* const Vsm1 = sm + 2 * KS_STRIDE + VT_STRIDE;

    const int t = threadIdx.x, lane = t & 31, warp = t >> 5;
    const int g = lane >> 2, tt = lane & 3;
    const int qt = blockIdx.x;
    const int bh = blockIdx.y;

    float* const Pw = sm + 2 * KS_STRIDE + 2 * VT_STRIDE + warp * P_STRIDE;

    const float* Qb  = g_Q + ((size_t)bh * SEQ + qt * 128) * 64;
    const float* Kb  = g_K + (size_t)bh * SEQ * 64;
    const float* Vtb = g_V + (size_t)bh * 64 * SEQ;   // [d][seq]

    // Q fragments (scale 1/8 and log2e folded in)
    unsigned Qf[8][4];
    const int qr = warp * 16;
    const float qs = 0.125f * LOG2E;
#pragma unroll
    for (int dq = 0; dq < 8; dq++) {
        Qf[dq][0] = f2tf(qs * Qb[(qr + g)     * 64 + dq * 8 + tt]);
        Qf[dq][1] = f2tf(qs * Qb[(qr + g + 8) * 64 + dq * 8 + tt]);
        Qf[dq][2] = f2tf(qs * Qb[(qr + g)     * 64 + dq * 8 + tt + 4]);
        Qf[dq][3] = f2tf(qs * Qb[(qr + g + 8) * 64 + dq * 8 + tt + 4]);
    }

    float Of[8][4];
#pragma unroll
    for (int nt = 0; nt < 8; nt++)
#pragma unroll
        for (int i = 0; i < 4; i++) Of[nt][i] = 0.f;
    float mrow[2] = {-1e30f, -1e30f};
    float lrow[2] = {0.f, 0.f};

    const int a_row = (lane & 7) + ((lane & 8) ? 8 : 0);
    const int a_col = (lane & 16) ? 4 : 0;
    const int b_row = (lane & 7) + ((lane & 16) ? 8 : 0);
    const int b_col = (lane & 8) ? 4 : 0;

    // ---- async fill helpers (8 x 16B per thread for K, same for V) ----
    // prologue: tile 0 -> buffer 0
    {
#pragma unroll
        for (int l = 0; l < 8; l++) {
            int s = t + 256 * l;
            int kr = s >> 4, kc = (s & 15) << 2;
            cp16(&Ksm0[kr * KP + kc], Kb + (size_t)kr * 64 + kc);
            int vr = s >> 5, vc = (s & 31) << 2;
            cp16(&Vsm0[vr * VP + vc], Vtb + (size_t)vr * SEQ + vc);
        }
        cp_commit();
    }

    for (int kt = 0; kt < SEQ / 128; kt++) {
        float* const Kcur = (kt & 1) ? Ksm1 : Ksm0;
        float* const Vcur = (kt & 1) ? Vsm1 : Vsm0;
        float* const Knxt = (kt & 1) ? Ksm0 : Ksm1;
        float* const Vnxt = (kt & 1) ? Vsm0 : Vsm1;

        cp_wait<0>();          // current tile resident
        __syncthreads();

        // issue next tile into the other buffer (overlaps with compute below)
        if (kt < SEQ / 128 - 1) {
            const float* Kp = Kb + (size_t)(kt + 1) * 128 * 64;
            const float* Vp = Vtb + (kt + 1) * 128;
#pragma unroll
            for (int l = 0; l < 8; l++) {
                int s = t + 256 * l;
                int kr = s >> 4, kc = (s & 15) << 2;
                cp16(&Knxt[kr * KP + kc], Kp + (size_t)kr * 64 + kc);
                int vr = s >> 5, vc = (s & 31) << 2;
                cp16(&Vnxt[vr * VP + vc], Vp + (size_t)vr * SEQ + vc);
            }
            cp_commit();
        }

#pragma unroll
        for (int hf = 0; hf < 2; hf++) {
            const int hk = hf * 64;

            // ---- S = Q K^T over this 64-key half ----
            float sf[8][4];
#pragma unroll
            for (int nt = 0; nt < 8; nt++)
#pragma unroll
                for (int i = 0; i < 4; i++) sf[nt][i] = 0.f;

#pragma unroll
            for (int dq = 0; dq < 8; dq++) {
                unsigned b[8][2];
#pragma unroll
                for (int np = 0; np < 4; np++)
                    ldsm4(b[np * 2][0], b[np * 2][1], b[np * 2 + 1][0], b[np * 2 + 1][1],
                          &Kcur[(hk + np * 16 + b_row) * KP + dq * 8 + b_col]);
#pragma unroll
                for (int nt = 0; nt < 8; nt++)
                    mma8(sf[nt], Qf[dq][0], Qf[dq][1], Qf[dq][2], Qf[dq][3],
                         b[nt][0], b[nt][1]);
            }

            // ---- online softmax in exp2 domain ----
            float alpha[2];
#pragma unroll
            for (int rp = 0; rp < 2; rp++) {
                float mx = -1e30f;
#pragma unroll
                for (int nt = 0; nt < 8; nt++)
                    mx = fmaxf(mx, fmaxf(sf[nt][rp * 2], sf[nt][rp * 2 + 1]));
                mx = fmaxf(mx, __shfl_xor_sync(0xffffffffu, mx, 1));
                mx = fmaxf(mx, __shfl_xor_sync(0xffffffffu, mx, 2));
                float nm = fmaxf(mrow[rp], mx);
                float sum = 0.f;
#pragma unroll
                for (int nt = 0; nt < 8; nt++) {
                    float p0 = exp2f(sf[nt][rp * 2]     - nm);
                    float p1 = exp2f(sf[nt][rp * 2 + 1] - nm);
                    sf[nt][rp * 2] = p0; sf[nt][rp * 2 + 1] = p1;
                    sum += p0 + p1;
                }
                sum += __shfl_xor_sync(0xffffffffu, sum, 1);
                sum += __shfl_xor_sync(0xffffffffu, sum, 2);
                alpha[rp] = exp2f(mrow[rp] - nm);
                mrow[rp] = nm;
                lrow[rp] = lrow[rp] * alpha[rp] + sum;
            }
#pragma unroll
            for (int nt = 0; nt < 8; nt++) {
                Of[nt][0] *= alpha[0]; Of[nt][1] *= alpha[0];
                Of[nt][2] *= alpha[1]; Of[nt][3] *= alpha[1];
            }

            // ---- stage P (tf32) into per-warp smem, reload as A-frags ----
            __syncwarp();
#pragma unroll
            for (int nt = 0; nt < 8; nt++) {
                float2 v0; v0.x = f2tff(sf[nt][0]); v0.y = f2tff(sf[nt][1]);
                float2 v1; v1.x = f2tff(sf[nt][2]); v1.y = f2tff(sf[nt][3]);
                *(float2*)&Pw[g       * PP + nt * 8 + 2 * tt] = v0;
                *(float2*)&Pw[(g + 8) * PP + nt * 8 + 2 * tt] = v1;
            }
            __syncwarp();

            // ---- O += P V ----
#pragma unroll
            for (int kq = 0; kq < 8; kq++) {
                unsigned a0, a1, a2, a3;
                ldsm4(a0, a1, a2, a3, &Pw[a_row * PP + kq * 8 + a_col]);
                unsigned vb[8][2];
#pragma unroll
                for (int np = 0; np < 4; np++)
                    ldsm4(vb[np * 2][0], vb[np * 2][1], vb[np * 2 + 1][0], vb[np * 2 + 1][1],
                          &Vcur[(np * 16 + b_row) * VP + hk + kq * 8 + b_col]);
#pragma unroll
                for (int nt = 0; nt < 8; nt++)
                    mma8(Of[nt], a0, a1, a2, a3, vb[nt][0], vb[nt][1]);
            }
        }
        __syncthreads();   // all warps done with Kcur/Vcur before next overwrite
    }

    const int b = bh >> 4, h = bh & 15;
    const float inv0 = 1.f / lrow[0], inv1 = 1.f / lrow[1];
    const int row = qt * 128 + warp * 16 + g;
#pragma unroll
    for (int nt = 0; nt < 8; nt++) {
        size_t base  = ((size_t)(b * SEQ + row))     * D_MODEL + h * 64 + nt * 8 + 2 * tt;
        size_t base2 = ((size_t)(b * SEQ + row + 8)) * D_MODEL + h * 64 + nt * 8 + 2 * tt;
        float2 v0; v0.x = Of[nt][0] * inv0; v0.y = Of[nt][1] * inv0;
        float2 v1; v1.x = Of[nt][2] * inv1; v1.y = Of[nt][3] * inv1;
        *(float2*)&g_ctx[base]  = v0;
        *(float2*)&g_ctx[base2] = v1;
    }
}

extern "C" void kernel_launch(void* const* d_in, const int* in_sizes, int n_in,
                              void* d_out, int out_size)
{
    const float* query = (const float*)d_in[0];
    const float* key   = (const float*)d_in[1];
    const float* value = (const float*)d_in[2];
    const float* Wq    = (const float*)d_in[3];
    const float* bq    = (const float*)d_in[4];
    const float* Wk    = (const float*)d_in[5];
    const float* bk    = (const float*)d_in[6];
    const float* Wv    = (const float*)d_in[7];
    const float* bv    = (const float*)d_in[8];
    const float* Wo    = (const float*)d_in[9];
    const float* bo    = (const float*)d_in[10];
    float* out = (float*)d_out;

    float* gQ;  cudaGetSymbolAddress((void**)&gQ,  g_Q);
    float* gK;  cudaGetSymbolAddress((void**)&gK,  g_K);
    float* gV;  cudaGetSymbolAddress((void**)&gV,  g_V);
    float* gC;  cudaGetSymbolAddress((void**)&gC,  g_ctx);

    cudaFuncSetAttribute(attn_tf32, cudaFuncAttributeMaxDynamicSharedMemorySize,
                         ATTN_SMEM_BYTES);

    dim3 ggrid(MTOT / 128, D_MODEL / 128);
    gemm_tf32<<<ggrid, 256>>>(query, Wq, bq, gQ, 1);
    gemm_tf32<<<ggrid, 256>>>(key,   Wk, bk, gK, 1);
    gemm_tf32<<<ggrid, 256>>>(value, Wv, bv, gV, 2);

    dim3 agrid(SEQ / 128, BATCH * NUM_HEADS);
    attn_tf32<<<agrid, 256, ATTN_SMEM_BYTES>>>();

    gemm_tf32<<<ggrid, 256>>>(gC, Wo, bo, out, 0);
}

// round 5
// speedup vs baseline: 4.8018x; 1.2837x over previous
#include <cuda_runtime.h>
#include <cuda_fp16.h>

#define D_MODEL   1024
#define NUM_HEADS 16
#define SEQ       2048
#define BATCH     2
#define MTOT      (BATCH*SEQ)   /* 4096 */
#define LOG2E     1.4426950408889634f

// Scratch (allocation-free rule: __device__ globals).
__device__ __half g_Q[(size_t)MTOT * D_MODEL];   // [b,h,s,d], pre-scaled by 0.125*log2e
__device__ __half g_K[(size_t)MTOT * D_MODEL];   // [b,h,s,d]
__device__ __half g_V[(size_t)MTOT * D_MODEL];   // TRANSPOSED [b,h,d,s]
__device__ float  g_ctx[(size_t)MTOT * D_MODEL];

__device__ __forceinline__ unsigned f2tf(float x) {
    unsigned r; asm("cvt.rna.tf32.f32 %0, %1;" : "=r"(r) : "f"(x)); return r;
}
__device__ __forceinline__ float f2tff(float x) { return __uint_as_float(f2tf(x)); }

__device__ __forceinline__ void ldsm4(unsigned& r0, unsigned& r1, unsigned& r2, unsigned& r3,
                                      const void* p) {
    unsigned a = (unsigned)__cvta_generic_to_shared(p);
    asm volatile("ldmatrix.sync.aligned.m8n8.x4.shared.b16 {%0,%1,%2,%3}, [%4];"
                 : "=r"(r0), "=r"(r1), "=r"(r2), "=r"(r3) : "r"(a));
}
// tf32 mma (GEMMs)
__device__ __forceinline__ void mma8(float* c, unsigned a0, unsigned a1, unsigned a2, unsigned a3,
                                     unsigned b0, unsigned b1) {
    asm volatile("mma.sync.aligned.m16n8k8.row.col.f32.tf32.tf32.f32 "
                 "{%0,%1,%2,%3},{%4,%5,%6,%7},{%8,%9},{%0,%1,%2,%3};"
                 : "+f"(c[0]), "+f"(c[1]), "+f"(c[2]), "+f"(c[3])
                 : "r"(a0), "r"(a1), "r"(a2), "r"(a3), "r"(b0), "r"(b1));
}
// fp16 mma (attention), fp32 accumulate
__device__ __forceinline__ void mma16(float* c, unsigned a0, unsigned a1, unsigned a2, unsigned a3,
                                      unsigned b0, unsigned b1) {
    asm volatile("mma.sync.aligned.m16n8k16.row.col.f32.f16.f16.f32 "
                 "{%0,%1,%2,%3},{%4,%5,%6,%7},{%8,%9},{%0,%1,%2,%3};"
                 : "+f"(c[0]), "+f"(c[1]), "+f"(c[2]), "+f"(c[3])
                 : "r"(a0), "r"(a1), "r"(a2), "r"(a3), "r"(b0), "r"(b1));
}
__device__ __forceinline__ void cp16(void* smem_dst, const void* gsrc) {
    unsigned d = (unsigned)__cvta_generic_to_shared(smem_dst);
    asm volatile("cp.async.cg.shared.global [%0], [%1], 16;\n" :: "r"(d), "l"(gsrc));
}
__device__ __forceinline__ void cp_commit() { asm volatile("cp.async.commit_group;\n"); }
template <int N> __device__ __forceinline__ void cp_wait() {
    asm volatile("cp.async.wait_group %0;\n" :: "n"(N));
}

// ------------------------- tf32 GEMM: C = A * W^T + bias -------------------------
// mode 0: fp32 [m,n]; mode 1: fp16 headsplit [b,h,s,d] (*oscale);
// mode 2: fp16 headsplit TRANSPOSED [b,h,d,s]
#define GP 36

__global__ __launch_bounds__(256, 2) void gemm_tf32(
    const float* __restrict__ A, const float* __restrict__ W,
    const float* __restrict__ bias, void* __restrict__ Cv, int mode, float oscale)
{
    __shared__ float As[128 * GP];
    __shared__ float Bs[128 * GP];
    const int t = threadIdx.x, lane = t & 31, warp = t >> 5;
    const int wm = warp >> 1, wn = warp & 1;
    const int g = lane >> 2, tt = lane & 3;
    const int bm = blockIdx.x, bn = blockIdx.y;

    float acc[2][8][4];
#pragma unroll
    for (int mt = 0; mt < 2; mt++)
#pragma unroll
        for (int nt = 0; nt < 8; nt++)
#pragma unroll
            for (int i = 0; i < 4; i++) acc[mt][nt][i] = 0.f;

    const float* Ap = A + (size_t)bm * 128 * 1024;
    const float* Wp = W + (size_t)bn * 128 * 1024;

    const int a_row = (lane & 7) + ((lane & 8) ? 8 : 0);
    const int a_col = (lane & 16) ? 4 : 0;
    const int b_row = (lane & 7) + ((lane & 16) ? 8 : 0);
    const int b_col = (lane & 8) ? 4 : 0;

    for (int k0 = 0; k0 < 1024; k0 += 32) {
#pragma unroll
        for (int l = 0; l < 4; l++) {
            int s = t + 256 * l;
            int m = s >> 3;
            int c4 = (s & 7) << 2;
            float4 av = *(const float4*)(Ap + (size_t)m * 1024 + k0 + c4);
            float4 as; as.x = f2tff(av.x); as.y = f2tff(av.y); as.z = f2tff(av.z); as.w = f2tff(av.w);
            *(float4*)&As[m * GP + c4] = as;
            float4 wv = *(const float4*)(Wp + (size_t)m * 1024 + k0 + c4);
            float4 ws; ws.x = f2tff(wv.x); ws.y = f2tff(wv.y); ws.z = f2tff(wv.z); ws.w = f2tff(wv.w);
            *(float4*)&Bs[m * GP + c4] = ws;
        }
        __syncthreads();
#pragma unroll
        for (int kq = 0; kq < 32; kq += 8) {
            unsigned a[2][4];
#pragma unroll
            for (int mt = 0; mt < 2; mt++) {
                int base = wm * 32 + mt * 16;
                ldsm4(a[mt][0], a[mt][1], a[mt][2], a[mt][3],
                      &As[(base + a_row) * GP + kq + a_col]);
            }
            unsigned b[8][2];
#pragma unroll
            for (int np = 0; np < 4; np++) {
                int nb = wn * 64 + np * 16;
                ldsm4(b[np * 2][0], b[np * 2][1], b[np * 2 + 1][0], b[np * 2 + 1][1],
                      &Bs[(nb + b_row) * GP + kq + b_col]);
            }
#pragma unroll
            for (int mt = 0; mt < 2; mt++)
#pragma unroll
                for (int nt = 0; nt < 8; nt++)
                    mma8(acc[mt][nt], a[mt][0], a[mt][1], a[mt][2], a[mt][3],
                         b[nt][0], b[nt][1]);
        }
        __syncthreads();
    }

#pragma unroll
    for (int mt = 0; mt < 2; mt++) {
        int row0 = bm * 128 + wm * 32 + mt * 16 + g;
#pragma unroll
        for (int nt = 0; nt < 8; nt++) {
            int cc = bn * 128 + wn * 64 + nt * 8 + 2 * tt;
            float2 bb = *(const float2*)&bias[cc];
#pragma unroll
            for (int rp = 0; rp < 2; rp++) {
                int row = row0 + rp * 8;
                float2 v;
                v.x = acc[mt][nt][rp * 2 + 0] + bb.x;
                v.y = acc[mt][nt][rp * 2 + 1] + bb.y;
                int b = row >> 11, sq = row & (SEQ - 1);
                int h = cc >> 6, dd = cc & 63;
                if (mode == 1) {
                    __half* C = (__half*)Cv;
                    __half2 hv = __floats2half2_rn(v.x * oscale, v.y * oscale);
                    *(__half2*)&C[((size_t)((b * NUM_HEADS + h) * SEQ + sq) << 6) + dd] = hv;
                } else if (mode == 2) {
                    __half* C = (__half*)Cv;
                    size_t base = (size_t)((b * NUM_HEADS + h) * 64 + dd) * SEQ + sq;
                    C[base] = __float2half_rn(v.x);
                    C[base + SEQ] = __float2half_rn(v.y);
                } else {
                    float* C = (float*)Cv;
                    *(float2*)&C[(size_t)row * D_MODEL + cc] = v;
                }
            }
        }
    }
}

// ------------------------- flash attention, fp16 mma -------------------------
// 8 warps, Br=128, key tiles of 128 double-buffered via cp.async.
// All operands fp16 (same mantissa as tf32), accumulation fp32.
#define KPH 72    /* K smem pitch in halves (d=64 + 8)        */
#define VPH 136   /* V^T smem pitch in halves (keys=128 + 8)  */
#define PPH 72    /* P staging pitch in halves (64 + 8)       */
#define KS_H (128 * KPH)   /* 9216 halves */
#define VT_H (64 * VPH)    /* 8704 halves */
#define P_H  (16 * PPH)    /* 1152 halves */
#define ATTN_SMEM_BYTES ((2 * KS_H + 2 * VT_H + 8 * P_H) * 2)  /* 90112 */

__global__ __launch_bounds__(256, 1) void attn_f16()
{
    extern __shared__ __half smh[];
    __half* const Ksm0 = smh;
    __half* const Ksm1 = smh + KS_H;
    __half* const Vsm0 = smh + 2 * KS_H;
    __half* const Vsm1 = smh + 2 * KS_H + VT_H;

    const int t = threadIdx.x, lane = t & 31, warp = t >> 5;
    const int g = lane >> 2, tt = lane & 3;
    const int qt = blockIdx.x;
    const int bh = blockIdx.y;

    __half* const Pw = smh + 2 * KS_H + 2 * VT_H + warp * P_H;

    const __half* Qb  = g_Q + ((size_t)bh * SEQ + qt * 128) * 64;
    const __half* Kb  = g_K + (size_t)bh * SEQ * 64;
    const __half* Vtb = g_V + (size_t)bh * 64 * SEQ;   // [d][seq]

    // Q A-fragments in registers (scale already folded into g_Q)
    unsigned Qf[4][4];
    const int qr = warp * 16;
#pragma unroll
    for (int dq = 0; dq < 4; dq++) {
        Qf[dq][0] = *(const unsigned*)(Qb + (qr + g)     * 64 + dq * 16 + 2 * tt);
        Qf[dq][1] = *(const unsigned*)(Qb + (qr + g + 8) * 64 + dq * 16 + 2 * tt);
        Qf[dq][2] = *(const unsigned*)(Qb + (qr + g)     * 64 + dq * 16 + 8 + 2 * tt);
        Qf[dq][3] = *(const unsigned*)(Qb + (qr + g + 8) * 64 + dq * 16 + 8 + 2 * tt);
    }

    float Of[8][4];
#pragma unroll
    for (int nt = 0; nt < 8; nt++)
#pragma unroll
        for (int i = 0; i < 4; i++) Of[nt][i] = 0.f;
    float mrow[2] = {-1e30f, -1e30f};
    float lrow[2] = {0.f, 0.f};

    const int a_row  = (lane & 7) + ((lane & 8) ? 8 : 0);   // A-frag row
    const int a_col8 = (lane & 16) ? 8 : 0;                 // A-frag k offset
    const int b_row  = (lane & 7) + ((lane & 16) ? 8 : 0);  // B-frag row (n)
    const int b_col8 = (lane & 8) ? 8 : 0;                  // B-frag k offset

    // ---- prologue: tile 0 -> buffer 0 (4+4 cp.async per thread) ----
    {
#pragma unroll
        for (int l = 0; l < 4; l++) {
            int s = t + 256 * l;
            int kr = s >> 3, kc = (s & 7) * 8;
            cp16(&Ksm0[kr * KPH + kc], Kb + (size_t)kr * 64 + kc);
            int vr = s >> 4, vc = (s & 15) * 8;
            cp16(&Vsm0[vr * VPH + vc], Vtb + (size_t)vr * SEQ + vc);
        }
        cp_commit();
    }

    for (int kt = 0; kt < SEQ / 128; kt++) {
        __half* const Kcur = (kt & 1) ? Ksm1 : Ksm0;
        __half* const Vcur = (kt & 1) ? Vsm1 : Vsm0;
        __half* const Knxt = (kt & 1) ? Ksm0 : Ksm1;
        __half* const Vnxt = (kt & 1) ? Vsm0 : Vsm1;

        cp_wait<0>();
        __syncthreads();

        if (kt < SEQ / 128 - 1) {
            const __half* Kp = Kb + (size_t)(kt + 1) * 128 * 64;
            const __half* Vp = Vtb + (kt + 1) * 128;
#pragma unroll
            for (int l = 0; l < 4; l++) {
                int s = t + 256 * l;
                int kr = s >> 3, kc = (s & 7) * 8;
                cp16(&Knxt[kr * KPH + kc], Kp + (size_t)kr * 64 + kc);
                int vr = s >> 4, vc = (s & 15) * 8;
                cp16(&Vnxt[vr * VPH + vc], Vp + (size_t)vr * SEQ + vc);
            }
            cp_commit();
        }

#pragma unroll
        for (int hf = 0; hf < 2; hf++) {
            const int hk = hf * 64;

            // ---- S = Q K^T (k-dim d=64, 4 steps of k16) ----
            float sf[8][4];
#pragma unroll
            for (int nt = 0; nt < 8; nt++)
#pragma unroll
                for (int i = 0; i < 4; i++) sf[nt][i] = 0.f;

#pragma unroll
            for (int dq = 0; dq < 4; dq++) {
                unsigned b[8][2];
#pragma unroll
                for (int np = 0; np < 4; np++)
                    ldsm4(b[np * 2][0], b[np * 2][1], b[np * 2 + 1][0], b[np * 2 + 1][1],
                          &Kcur[(hk + np * 16 + b_row) * KPH + dq * 16 + b_col8]);
#pragma unroll
                for (int nt = 0; nt < 8; nt++)
                    mma16(sf[nt], Qf[dq][0], Qf[dq][1], Qf[dq][2], Qf[dq][3],
                          b[nt][0], b[nt][1]);
            }

            // ---- online softmax in exp2 domain ----
            float alpha[2];
#pragma unroll
            for (int rp = 0; rp < 2; rp++) {
                float mx = -1e30f;
#pragma unroll
                for (int nt = 0; nt < 8; nt++)
                    mx = fmaxf(mx, fmaxf(sf[nt][rp * 2], sf[nt][rp * 2 + 1]));
                mx = fmaxf(mx, __shfl_xor_sync(0xffffffffu, mx, 1));
                mx = fmaxf(mx, __shfl_xor_sync(0xffffffffu, mx, 2));
                float nm = fmaxf(mrow[rp], mx);
                float sum = 0.f;
#pragma unroll
                for (int nt = 0; nt < 8; nt++) {
                    float p0 = exp2f(sf[nt][rp * 2]     - nm);
                    float p1 = exp2f(sf[nt][rp * 2 + 1] - nm);
                    sf[nt][rp * 2] = p0; sf[nt][rp * 2 + 1] = p1;
                    sum += p0 + p1;
                }
                sum += __shfl_xor_sync(0xffffffffu, sum, 1);
                sum += __shfl_xor_sync(0xffffffffu, sum, 2);
                alpha[rp] = exp2f(mrow[rp] - nm);
                mrow[rp] = nm;
                lrow[rp] = lrow[rp] * alpha[rp] + sum;
            }
#pragma unroll
            for (int nt = 0; nt < 8; nt++) {
                Of[nt][0] *= alpha[0]; Of[nt][1] *= alpha[0];
                Of[nt][2] *= alpha[1]; Of[nt][3] *= alpha[1];
            }

            // ---- stage P (fp16) into per-warp smem ----
            __syncwarp();
#pragma unroll
            for (int nt = 0; nt < 8; nt++) {
                __half2 h0 = __floats2half2_rn(sf[nt][0], sf[nt][1]);
                __half2 h1 = __floats2half2_rn(sf[nt][2], sf[nt][3]);
                *(__half2*)&Pw[g       * PPH + nt * 8 + 2 * tt] = h0;
                *(__half2*)&Pw[(g + 8) * PPH + nt * 8 + 2 * tt] = h1;
            }
            __syncwarp();

            // ---- O += P V (k-dim keys=64, 4 steps of k16) ----
#pragma unroll
            for (int kq = 0; kq < 4; kq++) {
                unsigned a0, a1, a2, a3;
                ldsm4(a0, a1, a2, a3, &Pw[a_row * PPH + kq * 16 + a_col8]);
                unsigned vb[8][2];
#pragma unroll
                for (int np = 0; np < 4; np++)
                    ldsm4(vb[np * 2][0], vb[np * 2][1], vb[np * 2 + 1][0], vb[np * 2 + 1][1],
                          &Vcur[(np * 16 + b_row) * VPH + hk + kq * 16 + b_col8]);
#pragma unroll
                for (int nt = 0; nt < 8; nt++)
                    mma16(Of[nt], a0, a1, a2, a3, vb[nt][0], vb[nt][1]);
            }
        }
        __syncthreads();
    }

    const int b = bh >> 4, h = bh & 15;
    const float inv0 = 1.f / lrow[0], inv1 = 1.f / lrow[1];
    const int row = qt * 128 + warp * 16 + g;
#pragma unroll
    for (int nt = 0; nt < 8; nt++) {
        size_t base  = ((size_t)(b * SEQ + row))     * D_MODEL + h * 64 + nt * 8 + 2 * tt;
        size_t base2 = ((size_t)(b * SEQ + row + 8)) * D_MODEL + h * 64 + nt * 8 + 2 * tt;
        float2 v0; v0.x = Of[nt][0] * inv0; v0.y = Of[nt][1] * inv0;
        float2 v1; v1.x = Of[nt][2] * inv1; v1.y = Of[nt][3] * inv1;
        *(float2*)&g_ctx[base]  = v0;
        *(float2*)&g_ctx[base2] = v1;
    }
}

extern "C" void kernel_launch(void* const* d_in, const int* in_sizes, int n_in,
                              void* d_out, int out_size)
{
    const float* query = (const float*)d_in[0];
    const float* key   = (const float*)d_in[1];
    const float* value = (const float*)d_in[2];
    const float* Wq    = (const float*)d_in[3];
    const float* bq    = (const float*)d_in[4];
    const float* Wk    = (const float*)d_in[5];
    const float* bk    = (const float*)d_in[6];
    const float* Wv    = (const float*)d_in[7];
    const float* bv    = (const float*)d_in[8];
    const float* Wo    = (const float*)d_in[9];
    const float* bo    = (const float*)d_in[10];
    float* out = (float*)d_out;

    __half* gQ;  cudaGetSymbolAddress((void**)&gQ,  g_Q);
    __half* gK;  cudaGetSymbolAddress((void**)&gK,  g_K);
    __half* gV;  cudaGetSymbolAddress((void**)&gV,  g_V);
    float*  gC;  cudaGetSymbolAddress((void**)&gC,  g_ctx);

    cudaFuncSetAttribute(attn_f16, cudaFuncAttributeMaxDynamicSharedMemorySize,
                         ATTN_SMEM_BYTES);

    dim3 ggrid(MTOT / 128, D_MODEL / 128);
    gemm_tf32<<<ggrid, 256>>>(query, Wq, bq, gQ, 1, 0.125f * LOG2E);
    gemm_tf32<<<ggrid, 256>>>(key,   Wk, bk, gK, 1, 1.0f);
    gemm_tf32<<<ggrid, 256>>>(value, Wv, bv, gV, 2, 1.0f);

    dim3 agrid(SEQ / 128, BATCH * NUM_HEADS);
    attn_f16<<<agrid, 256, ATTN_SMEM_BYTES>>>();

    gemm_tf32<<<ggrid, 256>>>(gC, Wo, bo, out, 0, 1.0f);
}

// round 6
// speedup vs baseline: 5.9043x; 1.2296x over previous
#include <cuda_runtime.h>
#include <cuda_fp16.h>

#define D_MODEL   1024
#define NUM_HEADS 16
#define SEQ       2048
#define BATCH     2
#define MTOT      (BATCH*SEQ)   /* 4096 */
#define LOG2E     1.4426950408889634f

// Scratch (allocation-free rule: __device__ globals).
__device__ __half g_Q[(size_t)MTOT * D_MODEL];   // [b,h,s,d], pre-scaled by 0.125*log2e
__device__ __half g_K[(size_t)MTOT * D_MODEL];   // [b,h,s,d]
__device__ __half g_V[(size_t)MTOT * D_MODEL];   // TRANSPOSED [b,h,d,s]
__device__ float  g_ctx[(size_t)MTOT * D_MODEL];

__device__ __forceinline__ void ldsm4(unsigned& r0, unsigned& r1, unsigned& r2, unsigned& r3,
                                      const void* p) {
    unsigned a = (unsigned)__cvta_generic_to_shared(p);
    asm volatile("ldmatrix.sync.aligned.m8n8.x4.shared.b16 {%0,%1,%2,%3}, [%4];"
                 : "=r"(r0), "=r"(r1), "=r"(r2), "=r"(r3) : "r"(a));
}
// fp16 mma, fp32 accumulate
__device__ __forceinline__ void mma16(float* c, unsigned a0, unsigned a1, unsigned a2, unsigned a3,
                                      unsigned b0, unsigned b1) {
    asm volatile("mma.sync.aligned.m16n8k16.row.col.f32.f16.f16.f32 "
                 "{%0,%1,%2,%3},{%4,%5,%6,%7},{%8,%9},{%0,%1,%2,%3};"
                 : "+f"(c[0]), "+f"(c[1]), "+f"(c[2]), "+f"(c[3])
                 : "r"(a0), "r"(a1), "r"(a2), "r"(a3), "r"(b0), "r"(b1));
}
__device__ __forceinline__ void cp16(void* smem_dst, const void* gsrc) {
    unsigned d = (unsigned)__cvta_generic_to_shared(smem_dst);
    asm volatile("cp.async.cg.shared.global [%0], [%1], 16;\n" :: "r"(d), "l"(gsrc));
}
__device__ __forceinline__ void cp_commit() { asm volatile("cp.async.commit_group;\n"); }
template <int N> __device__ __forceinline__ void cp_wait() {
    asm volatile("cp.async.wait_group %0;\n" :: "n"(N));
}

// ------------------------- fp16 GEMM: C = A * W^T + bias -------------------------
// A,W fp32 in gmem; converted to fp16 on smem fill. Accum fp32.
// mode 0: fp32 [m,n]; mode 1: fp16 headsplit [b,h,s,d] (*oscale);
// mode 2: fp16 headsplit TRANSPOSED [b,h,d,s]
#define KGP 40   /* smem pitch in halves: k=32 + 8 pad */

__global__ __launch_bounds__(256, 2) void gemm_f16(
    const float* __restrict__ A, const float* __restrict__ W,
    const float* __restrict__ bias, void* __restrict__ Cv, int mode, float oscale)
{
    __shared__ __half As[128 * KGP];
    __shared__ __half Bs[128 * KGP];
    const int t = threadIdx.x, lane = t & 31, warp = t >> 5;
    const int wm = warp >> 1, wn = warp & 1;
    const int g = lane >> 2, tt = lane & 3;
    const int bm = blockIdx.x, bn = blockIdx.y;

    float acc[2][8][4];
#pragma unroll
    for (int mt = 0; mt < 2; mt++)
#pragma unroll
        for (int nt = 0; nt < 8; nt++)
#pragma unroll
            for (int i = 0; i < 4; i++) acc[mt][nt][i] = 0.f;

    const float* Ap = A + (size_t)bm * 128 * 1024;
    const float* Wp = W + (size_t)bn * 128 * 1024;

    const int a_row  = (lane & 7) + ((lane & 8) ? 8 : 0);
    const int a_col8 = (lane & 16) ? 8 : 0;
    const int b_row  = (lane & 7) + ((lane & 16) ? 8 : 0);
    const int b_col8 = (lane & 8) ? 8 : 0;

    for (int k0 = 0; k0 < 1024; k0 += 32) {
#pragma unroll
        for (int l = 0; l < 4; l++) {
            int s = t + 256 * l;          // 0..1023 float4 slots
            int m = s >> 3;               // 0..127
            int c4 = (s & 7) << 2;        // 0..28 (halves)
            float4 av = *(const float4*)(Ap + (size_t)m * 1024 + k0 + c4);
            __half2 a01 = __floats2half2_rn(av.x, av.y);
            __half2 a23 = __floats2half2_rn(av.z, av.w);
            uint2 ua; ua.x = *(unsigned*)&a01; ua.y = *(unsigned*)&a23;
            *(uint2*)&As[m * KGP + c4] = ua;
            float4 wv = *(const float4*)(Wp + (size_t)m * 1024 + k0 + c4);
            __half2 w01 = __floats2half2_rn(wv.x, wv.y);
            __half2 w23 = __floats2half2_rn(wv.z, wv.w);
            uint2 uw; uw.x = *(unsigned*)&w01; uw.y = *(unsigned*)&w23;
            *(uint2*)&Bs[m * KGP + c4] = uw;
        }
        __syncthreads();
#pragma unroll
        for (int kq = 0; kq < 32; kq += 16) {
            unsigned a[2][4];
#pragma unroll
            for (int mt = 0; mt < 2; mt++) {
                int base = wm * 32 + mt * 16;
                ldsm4(a[mt][0], a[mt][1], a[mt][2], a[mt][3],
                      &As[(base + a_row) * KGP + kq + a_col8]);
            }
            unsigned b[8][2];
#pragma unroll
            for (int np = 0; np < 4; np++) {
                int nb = wn * 64 + np * 16;
                ldsm4(b[np * 2][0], b[np * 2][1], b[np * 2 + 1][0], b[np * 2 + 1][1],
                      &Bs[(nb + b_row) * KGP + kq + b_col8]);
            }
#pragma unroll
            for (int mt = 0; mt < 2; mt++)
#pragma unroll
                for (int nt = 0; nt < 8; nt++)
                    mma16(acc[mt][nt], a[mt][0], a[mt][1], a[mt][2], a[mt][3],
                          b[nt][0], b[nt][1]);
        }
        __syncthreads();
    }

#pragma unroll
    for (int mt = 0; mt < 2; mt++) {
        int row0 = bm * 128 + wm * 32 + mt * 16 + g;
#pragma unroll
        for (int nt = 0; nt < 8; nt++) {
            int cc = bn * 128 + wn * 64 + nt * 8 + 2 * tt;
            float2 bb = *(const float2*)&bias[cc];
#pragma unroll
            for (int rp = 0; rp < 2; rp++) {
                int row = row0 + rp * 8;
                float2 v;
                v.x = acc[mt][nt][rp * 2 + 0] + bb.x;
                v.y = acc[mt][nt][rp * 2 + 1] + bb.y;
                int b = row >> 11, sq = row & (SEQ - 1);
                int h = cc >> 6, dd = cc & 63;
                if (mode == 1) {
                    __half* C = (__half*)Cv;
                    __half2 hv = __floats2half2_rn(v.x * oscale, v.y * oscale);
                    *(__half2*)&C[((size_t)((b * NUM_HEADS + h) * SEQ + sq) << 6) + dd] = hv;
                } else if (mode == 2) {
                    __half* C = (__half*)Cv;
                    size_t base = (size_t)((b * NUM_HEADS + h) * 64 + dd) * SEQ + sq;
                    C[base] = __float2half_rn(v.x);
                    C[base + SEQ] = __float2half_rn(v.y);
                } else {
                    float* C = (float*)Cv;
                    *(float2*)&C[(size_t)row * D_MODEL + cc] = v;
                }
            }
        }
    }
}

// ------------------------- flash attention, fp16 mma -------------------------
// 8 warps, Br=128, key tiles of 128 double-buffered via cp.async.
#define KPH 72    /* K smem pitch in halves (d=64 + 8)        */
#define VPH 136   /* V^T smem pitch in halves (keys=128 + 8)  */
#define PPH 72    /* P staging pitch in halves (64 + 8)       */
#define KS_H (128 * KPH)
#define VT_H (64 * VPH)
#define P_H  (16 * PPH)
#define ATTN_SMEM_BYTES ((2 * KS_H + 2 * VT_H + 8 * P_H) * 2)  /* 90112 */

__global__ __launch_bounds__(256, 1) void attn_f16()
{
    extern __shared__ __half smh[];
    __half* const Ksm0 = smh;
    __half* const Ksm1 = smh + KS_H;
    __half* const Vsm0 = smh + 2 * KS_H;
    __half* const Vsm1 = smh + 2 * KS_H + VT_H;

    const int t = threadIdx.x, lane = t & 31, warp = t >> 5;
    const int g = lane >> 2, tt = lane & 3;
    const int qt = blockIdx.x;
    const int bh = blockIdx.y;

    __half* const Pw = smh + 2 * KS_H + 2 * VT_H + warp * P_H;

    const __half* Qb  = g_Q + ((size_t)bh * SEQ + qt * 128) * 64;
    const __half* Kb  = g_K + (size_t)bh * SEQ * 64;
    const __half* Vtb = g_V + (size_t)bh * 64 * SEQ;

    unsigned Qf[4][4];
    const int qr = warp * 16;
#pragma unroll
    for (int dq = 0; dq < 4; dq++) {
        Qf[dq][0] = *(const unsigned*)(Qb + (qr + g)     * 64 + dq * 16 + 2 * tt);
        Qf[dq][1] = *(const unsigned*)(Qb + (qr + g + 8) * 64 + dq * 16 + 2 * tt);
        Qf[dq][2] = *(const unsigned*)(Qb + (qr + g)     * 64 + dq * 16 + 8 + 2 * tt);
        Qf[dq][3] = *(const unsigned*)(Qb + (qr + g + 8) * 64 + dq * 16 + 8 + 2 * tt);
    }

    float Of[8][4];
#pragma unroll
    for (int nt = 0; nt < 8; nt++)
#pragma unroll
        for (int i = 0; i < 4; i++) Of[nt][i] = 0.f;
    float mrow[2] = {-1e30f, -1e30f};
    float lrow[2] = {0.f, 0.f};

    const int a_row  = (lane & 7) + ((lane & 8) ? 8 : 0);
    const int a_col8 = (lane & 16) ? 8 : 0;
    const int b_row  = (lane & 7) + ((lane & 16) ? 8 : 0);
    const int b_col8 = (lane & 8) ? 8 : 0;

    {
#pragma unroll
        for (int l = 0; l < 4; l++) {
            int s = t + 256 * l;
            int kr = s >> 3, kc = (s & 7) * 8;
            cp16(&Ksm0[kr * KPH + kc], Kb + (size_t)kr * 64 + kc);
            int vr = s >> 4, vc = (s & 15) * 8;
            cp16(&Vsm0[vr * VPH + vc], Vtb + (size_t)vr * SEQ + vc);
        }
        cp_commit();
    }

    for (int kt = 0; kt < SEQ / 128; kt++) {
        __half* const Kcur = (kt & 1) ? Ksm1 : Ksm0;
        __half* const Vcur = (kt & 1) ? Vsm1 : Vsm0;
        __half* const Knxt = (kt & 1) ? Ksm0 : Ksm1;
        __half* const Vnxt = (kt & 1) ? Vsm0 : Vsm1;

        cp_wait<0>();
        __syncthreads();

        if (kt < SEQ / 128 - 1) {
            const __half* Kp = Kb + (size_t)(kt + 1) * 128 * 64;
            const __half* Vp = Vtb + (kt + 1) * 128;
#pragma unroll
            for (int l = 0; l < 4; l++) {
                int s = t + 256 * l;
                int kr = s >> 3, kc = (s & 7) * 8;
                cp16(&Knxt[kr * KPH + kc], Kp + (size_t)kr * 64 + kc);
                int vr = s >> 4, vc = (s & 15) * 8;
                cp16(&Vnxt[vr * VPH + vc], Vp + (size_t)vr * SEQ + vc);
            }
            cp_commit();
        }

#pragma unroll
        for (int hf = 0; hf < 2; hf++) {
            const int hk = hf * 64;

            float sf[8][4];
#pragma unroll
            for (int nt = 0; nt < 8; nt++)
#pragma unroll
                for (int i = 0; i < 4; i++) sf[nt][i] = 0.f;

#pragma unroll
            for (int dq = 0; dq < 4; dq++) {
                unsigned b[8][2];
#pragma unroll
                for (int np = 0; np < 4; np++)
                    ldsm4(b[np * 2][0], b[np * 2][1], b[np * 2 + 1][0], b[np * 2 + 1][1],
                          &Kcur[(hk + np * 16 + b_row) * KPH + dq * 16 + b_col8]);
#pragma unroll
                for (int nt = 0; nt < 8; nt++)
                    mma16(sf[nt], Qf[dq][0], Qf[dq][1], Qf[dq][2], Qf[dq][3],
                          b[nt][0], b[nt][1]);
            }

            float alpha[2];
#pragma unroll
            for (int rp = 0; rp < 2; rp++) {
                float mx = -1e30f;
#pragma unroll
                for (int nt = 0; nt < 8; nt++)
                    mx = fmaxf(mx, fmaxf(sf[nt][rp * 2], sf[nt][rp * 2 + 1]));
                mx = fmaxf(mx, __shfl_xor_sync(0xffffffffu, mx, 1));
                mx = fmaxf(mx, __shfl_xor_sync(0xffffffffu, mx, 2));
                float nm = fmaxf(mrow[rp], mx);
                float sum = 0.f;
#pragma unroll
                for (int nt = 0; nt < 8; nt++) {
                    float p0 = exp2f(sf[nt][rp * 2]     - nm);
                    float p1 = exp2f(sf[nt][rp * 2 + 1] - nm);
                    sf[nt][rp * 2] = p0; sf[nt][rp * 2 + 1] = p1;
                    sum += p0 + p1;
                }
                sum += __shfl_xor_sync(0xffffffffu, sum, 1);
                sum += __shfl_xor_sync(0xffffffffu, sum, 2);
                alpha[rp] = exp2f(mrow[rp] - nm);
                mrow[rp] = nm;
                lrow[rp] = lrow[rp] * alpha[rp] + sum;
            }
#pragma unroll
            for (int nt = 0; nt < 8; nt++) {
                Of[nt][0] *= alpha[0]; Of[nt][1] *= alpha[0];
                Of[nt][2] *= alpha[1]; Of[nt][3] *= alpha[1];
            }

            __syncwarp();
#pragma unroll
            for (int nt = 0; nt < 8; nt++) {
                __half2 h0 = __floats2half2_rn(sf[nt][0], sf[nt][1]);
                __half2 h1 = __floats2half2_rn(sf[nt][2], sf[nt][3]);
                *(__half2*)&Pw[g       * PPH + nt * 8 + 2 * tt] = h0;
                *(__half2*)&Pw[(g + 8) * PPH + nt * 8 + 2 * tt] = h1;
            }
            __syncwarp();

#pragma unroll
            for (int kq = 0; kq < 4; kq++) {
                unsigned a0, a1, a2, a3;
                ldsm4(a0, a1, a2, a3, &Pw[a_row * PPH + kq * 16 + a_col8]);
                unsigned vb[8][2];
#pragma unroll
                for (int np = 0; np < 4; np++)
                    ldsm4(vb[np * 2][0], vb[np * 2][1], vb[np * 2 + 1][0], vb[np * 2 + 1][1],
                          &Vcur[(np * 16 + b_row) * VPH + hk + kq * 16 + b_col8]);
#pragma unroll
                for (int nt = 0; nt < 8; nt++)
                    mma16(Of[nt], a0, a1, a2, a3, vb[nt][0], vb[nt][1]);
            }
        }
        __syncthreads();
    }

    const int b = bh >> 4, h = bh & 15;
    const float inv0 = 1.f / lrow[0], inv1 = 1.f / lrow[1];
    const int row = qt * 128 + warp * 16 + g;
#pragma unroll
    for (int nt = 0; nt < 8; nt++) {
        size_t base  = ((size_t)(b * SEQ + row))     * D_MODEL + h * 64 + nt * 8 + 2 * tt;
        size_t base2 = ((size_t)(b * SEQ + row + 8)) * D_MODEL + h * 64 + nt * 8 + 2 * tt;
        float2 v0; v0.x = Of[nt][0] * inv0; v0.y = Of[nt][1] * inv0;
        float2 v1; v1.x = Of[nt][2] * inv1; v1.y = Of[nt][3] * inv1;
        *(float2*)&g_ctx[base]  = v0;
        *(float2*)&g_ctx[base2] = v1;
    }
}

extern "C" void kernel_launch(void* const* d_in, const int* in_sizes, int n_in,
                              void* d_out, int out_size)
{
    const float* query = (const float*)d_in[0];
    const float* key   = (const float*)d_in[1];
    const float* value = (const float*)d_in[2];
    const float* Wq    = (const float*)d_in[3];
    const float* bq    = (const float*)d_in[4];
    const float* Wk    = (const float*)d_in[5];
    const float* bk    = (const float*)d_in[6];
    const float* Wv    = (const float*)d_in[7];
    const float* bv    = (const float*)d_in[8];
    const float* Wo    = (const float*)d_in[9];
    const float* bo    = (const float*)d_in[10];
    float* out = (float*)d_out;

    __half* gQ;  cudaGetSymbolAddress((void**)&gQ,  g_Q);
    __half* gK;  cudaGetSymbolAddress((void**)&gK,  g_K);
    __half* gV;  cudaGetSymbolAddress((void**)&gV,  g_V);
    float*  gC;  cudaGetSymbolAddress((void**)&gC,  g_ctx);

    cudaFuncSetAttribute(attn_f16, cudaFuncAttributeMaxDynamicSharedMemorySize,
                         ATTN_SMEM_BYTES);

    dim3 ggrid(MTOT / 128, D_MODEL / 128);
    gemm_f16<<<ggrid, 256>>>(query, Wq, bq, gQ, 1, 0.125f * LOG2E);
    gemm_f16<<<ggrid, 256>>>(key,   Wk, bk, gK, 1, 1.0f);
    gemm_f16<<<ggrid, 256>>>(value, Wv, bv, gV, 2, 1.0f);

    dim3 agrid(SEQ / 128, BATCH * NUM_HEADS);
    attn_f16<<<agrid, 256, ATTN_SMEM_BYTES>>>();

    gemm_f16<<<ggrid, 256>>>(gC, Wo, bo, out, 0, 1.0f);
}

// round 7
// speedup vs baseline: 6.3842x; 1.0813x over previous
#include <cuda_runtime.h>
#include <cuda_fp16.h>

#define D_MODEL   1024
#define NUM_HEADS 16
#define SEQ       2048
#define BATCH     2
#define MTOT      (BATCH*SEQ)   /* 4096 */
#define LOG2E     1.4426950408889634f

// Scratch (allocation-free rule: __device__ globals).
__device__ __half h_q[(size_t)MTOT * D_MODEL];
__device__ __half h_k[(size_t)MTOT * D_MODEL];
__device__ __half h_v[(size_t)MTOT * D_MODEL];
__device__ __half h_wq[(size_t)D_MODEL * D_MODEL];
__device__ __half h_wk[(size_t)D_MODEL * D_MODEL];
__device__ __half h_wv[(size_t)D_MODEL * D_MODEL];
__device__ __half h_wo[(size_t)D_MODEL * D_MODEL];
__device__ __half g_Q[(size_t)MTOT * D_MODEL];   // [b,h,s,d], pre-scaled by 0.125*log2e
__device__ __half g_K[(size_t)MTOT * D_MODEL];   // [b,h,s,d]
__device__ __half g_V[(size_t)MTOT * D_MODEL];   // TRANSPOSED [b,h,d,s]
__device__ __half g_ctx[(size_t)MTOT * D_MODEL]; // [m, D_MODEL] fp16

__device__ __forceinline__ void ldsm4(unsigned& r0, unsigned& r1, unsigned& r2, unsigned& r3,
                                      const void* p) {
    unsigned a = (unsigned)__cvta_generic_to_shared(p);
    asm volatile("ldmatrix.sync.aligned.m8n8.x4.shared.b16 {%0,%1,%2,%3}, [%4];"
                 : "=r"(r0), "=r"(r1), "=r"(r2), "=r"(r3) : "r"(a));
}
__device__ __forceinline__ void mma16(float* c, unsigned a0, unsigned a1, unsigned a2, unsigned a3,
                                      unsigned b0, unsigned b1) {
    asm volatile("mma.sync.aligned.m16n8k16.row.col.f32.f16.f16.f32 "
                 "{%0,%1,%2,%3},{%4,%5,%6,%7},{%8,%9},{%0,%1,%2,%3};"
                 : "+f"(c[0]), "+f"(c[1]), "+f"(c[2]), "+f"(c[3])
                 : "r"(a0), "r"(a1), "r"(a2), "r"(a3), "r"(b0), "r"(b1));
}
__device__ __forceinline__ void cp16(void* smem_dst, const void* gsrc) {
    unsigned d = (unsigned)__cvta_generic_to_shared(smem_dst);
    asm volatile("cp.async.cg.shared.global [%0], [%1], 16;\n" :: "r"(d), "l"(gsrc));
}
__device__ __forceinline__ void cp_commit() { asm volatile("cp.async.commit_group;\n"); }
template <int N> __device__ __forceinline__ void cp_wait() {
    asm volatile("cp.async.wait_group %0;\n" :: "n"(N));
}

// ------------------------- fp32 -> fp16 conversion (7 tensors, one launch) ----
struct CvtJobs { const float* src[7]; __half* dst[7]; int n[7]; };

__global__ __launch_bounds__(256) void cvt_f16(CvtJobs jobs)
{
    int j = blockIdx.y;
    int base = (blockIdx.x * 256 + threadIdx.x) * 8;
    if (base >= jobs.n[j]) return;
    const float4* s = (const float4*)(jobs.src[j] + base);
    float4 v0 = s[0], v1 = s[1];
    __half2 p0 = __floats2half2_rn(v0.x, v0.y);
    __half2 p1 = __floats2half2_rn(v0.z, v0.w);
    __half2 p2 = __floats2half2_rn(v1.x, v1.y);
    __half2 p3 = __floats2half2_rn(v1.z, v1.w);
    uint4 u; u.x = *(unsigned*)&p0; u.y = *(unsigned*)&p1;
    u.z = *(unsigned*)&p2; u.w = *(unsigned*)&p3;
    *(uint4*)(jobs.dst[j] + base) = u;
}

// ------------------------- fp16 GEMM, 3-stage cp.async pipeline ----------------
// C = A * W^T + bias. A:[M,1024] fp16, W:[1024,1024] fp16 (row n = output col).
// mode 0: fp32 [m,n]; mode 1: fp16 headsplit [b,h,s,d] (*oscale);
// mode 2: fp16 headsplit TRANSPOSED [b,h,d,s]
#define KGP 40         /* smem pitch halves: 32 + 8 pad */
#define GSTG (128 * KGP)            /* halves per matrix per stage: 5120 */
#define GSTAGE_H (2 * GSTG)         /* A+B per stage: 10240 halves */
#define GEMM_SMEM_BYTES (3 * GSTAGE_H * 2)   /* 61440 */

struct GemmJob { const __half* A; const __half* W; const float* bias;
                 void* C; int mode; float oscale; };
struct GemmJobs3 { GemmJob j[3]; };

__global__ __launch_bounds__(256, 2) void gemm_f16p(GemmJobs3 js)
{
    extern __shared__ __half sg[];
    const GemmJob jb = js.j[blockIdx.z];
    const int t = threadIdx.x, lane = t & 31, warp = t >> 5;
    const int wm = warp >> 1, wn = warp & 1;
    const int g = lane >> 2, tt = lane & 3;
    const int bm = blockIdx.x, bn = blockIdx.y;

    float acc[2][8][4];
#pragma unroll
    for (int mt = 0; mt < 2; mt++)
#pragma unroll
        for (int nt = 0; nt < 8; nt++)
#pragma unroll
            for (int i = 0; i < 4; i++) acc[mt][nt][i] = 0.f;

    const __half* Ap = jb.A + (size_t)bm * 128 * 1024;
    const __half* Wp = jb.W + (size_t)bn * 128 * 1024;

    const int a_row  = (lane & 7) + ((lane & 8) ? 8 : 0);
    const int a_col8 = (lane & 16) ? 8 : 0;
    const int b_row  = (lane & 7) + ((lane & 16) ? 8 : 0);
    const int b_col8 = (lane & 8) ? 8 : 0;

    // fill helper indices: s = t + 256*l, l=0..1 -> 512 slots of 16B
    const int fm0 = t >> 2, fc0 = (t & 3) * 8;           // l=0
    const int fm1 = (t + 256) >> 2, fc1 = ((t + 256) & 3) * 8;

    // prologue: stages 0 and 1
#pragma unroll
    for (int st = 0; st < 2; st++) {
        __half* Sa = sg + st * GSTAGE_H;
        __half* Sb = Sa + GSTG;
        int k0 = st * 32;
        cp16(&Sa[fm0 * KGP + fc0], Ap + (size_t)fm0 * 1024 + k0 + fc0);
        cp16(&Sa[fm1 * KGP + fc1], Ap + (size_t)fm1 * 1024 + k0 + fc1);
        cp16(&Sb[fm0 * KGP + fc0], Wp + (size_t)fm0 * 1024 + k0 + fc0);
        cp16(&Sb[fm1 * KGP + fc1], Wp + (size_t)fm1 * 1024 + k0 + fc1);
        cp_commit();
    }

    for (int ks = 0; ks < 32; ks++) {
        cp_wait<1>();
        __syncthreads();

        // issue stage ks+2 (possibly empty commit to keep group accounting uniform)
        if (ks + 2 < 32) {
            int st = (ks + 2) % 3;
            __half* Sa = sg + st * GSTAGE_H;
            __half* Sb = Sa + GSTG;
            int k0 = (ks + 2) * 32;
            cp16(&Sa[fm0 * KGP + fc0], Ap + (size_t)fm0 * 1024 + k0 + fc0);
            cp16(&Sa[fm1 * KGP + fc1], Ap + (size_t)fm1 * 1024 + k0 + fc1);
            cp16(&Sb[fm0 * KGP + fc0], Wp + (size_t)fm0 * 1024 + k0 + fc0);
            cp16(&Sb[fm1 * KGP + fc1], Wp + (size_t)fm1 * 1024 + k0 + fc1);
        }
        cp_commit();

        __half* Sa = sg + (ks % 3) * GSTAGE_H;
        __half* Sb = Sa + GSTG;
#pragma unroll
        for (int kq = 0; kq < 32; kq += 16) {
            unsigned a[2][4];
#pragma unroll
            for (int mt = 0; mt < 2; mt++) {
                int base = wm * 32 + mt * 16;
                ldsm4(a[mt][0], a[mt][1], a[mt][2], a[mt][3],
                      &Sa[(base + a_row) * KGP + kq + a_col8]);
            }
            unsigned b[8][2];
#pragma unroll
            for (int np = 0; np < 4; np++) {
                int nb = wn * 64 + np * 16;
                ldsm4(b[np * 2][0], b[np * 2][1], b[np * 2 + 1][0], b[np * 2 + 1][1],
                      &Sb[(nb + b_row) * KGP + kq + b_col8]);
            }
#pragma unroll
            for (int mt = 0; mt < 2; mt++)
#pragma unroll
                for (int nt = 0; nt < 8; nt++)
                    mma16(acc[mt][nt], a[mt][0], a[mt][1], a[mt][2], a[mt][3],
                          b[nt][0], b[nt][1]);
        }
        __syncthreads();
    }

#pragma unroll
    for (int mt = 0; mt < 2; mt++) {
        int row0 = bm * 128 + wm * 32 + mt * 16 + g;
#pragma unroll
        for (int nt = 0; nt < 8; nt++) {
            int cc = bn * 128 + wn * 64 + nt * 8 + 2 * tt;
            float2 bb = *(const float2*)&jb.bias[cc];
#pragma unroll
            for (int rp = 0; rp < 2; rp++) {
                int row = row0 + rp * 8;
                float2 v;
                v.x = acc[mt][nt][rp * 2 + 0] + bb.x;
                v.y = acc[mt][nt][rp * 2 + 1] + bb.y;
                int b = row >> 11, sq = row & (SEQ - 1);
                int h = cc >> 6, dd = cc & 63;
                if (jb.mode == 1) {
                    __half* C = (__half*)jb.C;
                    __half2 hv = __floats2half2_rn(v.x * jb.oscale, v.y * jb.oscale);
                    *(__half2*)&C[((size_t)((b * NUM_HEADS + h) * SEQ + sq) << 6) + dd] = hv;
                } else if (jb.mode == 2) {
                    __half* C = (__half*)jb.C;
                    size_t base = (size_t)((b * NUM_HEADS + h) * 64 + dd) * SEQ + sq;
                    C[base] = __float2half_rn(v.x);
                    C[base + SEQ] = __float2half_rn(v.y);
                } else {
                    float* C = (float*)jb.C;
                    *(float2*)&C[(size_t)row * D_MODEL + cc] = v;
                }
            }
        }
    }
}

// ------------------------- flash attention, fp16 mma -------------------------
#define KPH 72
#define VPH 136
#define PPH 72
#define KS_H (128 * KPH)
#define VT_H (64 * VPH)
#define P_H  (16 * PPH)
#define ATTN_SMEM_BYTES ((2 * KS_H + 2 * VT_H + 8 * P_H) * 2)  /* 90112 */

__global__ __launch_bounds__(256, 1) void attn_f16()
{
    extern __shared__ __half smh[];
    __half* const Ksm0 = smh;
    __half* const Ksm1 = smh + KS_H;
    __half* const Vsm0 = smh + 2 * KS_H;
    __half* const Vsm1 = smh + 2 * KS_H + VT_H;

    const int t = threadIdx.x, lane = t & 31, warp = t >> 5;
    const int g = lane >> 2, tt = lane & 3;
    const int qt = blockIdx.x;
    const int bh = blockIdx.y;

    __half* const Pw = smh + 2 * KS_H + 2 * VT_H + warp * P_H;

    const __half* Qb  = g_Q + ((size_t)bh * SEQ + qt * 128) * 64;
    const __half* Kb  = g_K + (size_t)bh * SEQ * 64;
    const __half* Vtb = g_V + (size_t)bh * 64 * SEQ;

    unsigned Qf[4][4];
    const int qr = warp * 16;
#pragma unroll
    for (int dq = 0; dq < 4; dq++) {
        Qf[dq][0] = *(const unsigned*)(Qb + (qr + g)     * 64 + dq * 16 + 2 * tt);
        Qf[dq][1] = *(const unsigned*)(Qb + (qr + g + 8) * 64 + dq * 16 + 2 * tt);
        Qf[dq][2] = *(const unsigned*)(Qb + (qr + g)     * 64 + dq * 16 + 8 + 2 * tt);
        Qf[dq][3] = *(const unsigned*)(Qb + (qr + g + 8) * 64 + dq * 16 + 8 + 2 * tt);
    }

    float Of[8][4];
#pragma unroll
    for (int nt = 0; nt < 8; nt++)
#pragma unroll
        for (int i = 0; i < 4; i++) Of[nt][i] = 0.f;
    float mrow[2] = {-1e30f, -1e30f};
    float lrow[2] = {0.f, 0.f};

    const int a_row  = (lane & 7) + ((lane & 8) ? 8 : 0);
    const int a_col8 = (lane & 16) ? 8 : 0;
    const int b_row  = (lane & 7) + ((lane & 16) ? 8 : 0);
    const int b_col8 = (lane & 8) ? 8 : 0;

    {
#pragma unroll
        for (int l = 0; l < 4; l++) {
            int s = t + 256 * l;
            int kr = s >> 3, kc = (s & 7) * 8;
            cp16(&Ksm0[kr * KPH + kc], Kb + (size_t)kr * 64 + kc);
            int vr = s >> 4, vc = (s & 15) * 8;
            cp16(&Vsm0[vr * VPH + vc], Vtb + (size_t)vr * SEQ + vc);
        }
        cp_commit();
    }

    for (int kt = 0; kt < SEQ / 128; kt++) {
        __half* const Kcur = (kt & 1) ? Ksm1 : Ksm0;
        __half* const Vcur = (kt & 1) ? Vsm1 : Vsm0;
        __half* const Knxt = (kt & 1) ? Ksm0 : Ksm1;
        __half* const Vnxt = (kt & 1) ? Vsm0 : Vsm1;

        cp_wait<0>();
        __syncthreads();

        if (kt < SEQ / 128 - 1) {
            const __half* Kp = Kb + (size_t)(kt + 1) * 128 * 64;
            const __half* Vp = Vtb + (kt + 1) * 128;
#pragma unroll
            for (int l = 0; l < 4; l++) {
                int s = t + 256 * l;
                int kr = s >> 3, kc = (s & 7) * 8;
                cp16(&Knxt[kr * KPH + kc], Kp + (size_t)kr * 64 + kc);
                int vr = s >> 4, vc = (s & 15) * 8;
                cp16(&Vnxt[vr * VPH + vc], Vp + (size_t)vr * SEQ + vc);
            }
            cp_commit();
        }

#pragma unroll
        for (int hf = 0; hf < 2; hf++) {
            const int hk = hf * 64;

            float sf[8][4];
#pragma unroll
            for (int nt = 0; nt < 8; nt++)
#pragma unroll
                for (int i = 0; i < 4; i++) sf[nt][i] = 0.f;

#pragma unroll
            for (int dq = 0; dq < 4; dq++) {
                unsigned b[8][2];
#pragma unroll
                for (int np = 0; np < 4; np++)
                    ldsm4(b[np * 2][0], b[np * 2][1], b[np * 2 + 1][0], b[np * 2 + 1][1],
                          &Kcur[(hk + np * 16 + b_row) * KPH + dq * 16 + b_col8]);
#pragma unroll
                for (int nt = 0; nt < 8; nt++)
                    mma16(sf[nt], Qf[dq][0], Qf[dq][1], Qf[dq][2], Qf[dq][3],
                          b[nt][0], b[nt][1]);
            }

            float alpha[2];
#pragma unroll
            for (int rp = 0; rp < 2; rp++) {
                float mx = -1e30f;
#pragma unroll
                for (int nt = 0; nt < 8; nt++)
                    mx = fmaxf(mx, fmaxf(sf[nt][rp * 2], sf[nt][rp * 2 + 1]));
                mx = fmaxf(mx, __shfl_xor_sync(0xffffffffu, mx, 1));
                mx = fmaxf(mx, __shfl_xor_sync(0xffffffffu, mx, 2));
                float nm = fmaxf(mrow[rp], mx);
                float sum = 0.f;
#pragma unroll
                for (int nt = 0; nt < 8; nt++) {
                    float p0 = exp2f(sf[nt][rp * 2]     - nm);
                    float p1 = exp2f(sf[nt][rp * 2 + 1] - nm);
                    sf[nt][rp * 2] = p0; sf[nt][rp * 2 + 1] = p1;
                    sum += p0 + p1;
                }
                sum += __shfl_xor_sync(0xffffffffu, sum, 1);
                sum += __shfl_xor_sync(0xffffffffu, sum, 2);
                alpha[rp] = exp2f(mrow[rp] - nm);
                mrow[rp] = nm;
                lrow[rp] = lrow[rp] * alpha[rp] + sum;
            }
#pragma unroll
            for (int nt = 0; nt < 8; nt++) {
                Of[nt][0] *= alpha[0]; Of[nt][1] *= alpha[0];
                Of[nt][2] *= alpha[1]; Of[nt][3] *= alpha[1];
            }

            __syncwarp();
#pragma unroll
            for (int nt = 0; nt < 8; nt++) {
                __half2 h0 = __floats2half2_rn(sf[nt][0], sf[nt][1]);
                __half2 h1 = __floats2half2_rn(sf[nt][2], sf[nt][3]);
                *(__half2*)&Pw[g       * PPH + nt * 8 + 2 * tt] = h0;
                *(__half2*)&Pw[(g + 8) * PPH + nt * 8 + 2 * tt] = h1;
            }
            __syncwarp();

#pragma unroll
            for (int kq = 0; kq < 4; kq++) {
                unsigned a0, a1, a2, a3;
                ldsm4(a0, a1, a2, a3, &Pw[a_row * PPH + kq * 16 + a_col8]);
                unsigned vb[8][2];
#pragma unroll
                for (int np = 0; np < 4; np++)
                    ldsm4(vb[np * 2][0], vb[np * 2][1], vb[np * 2 + 1][0], vb[np * 2 + 1][1],
                          &Vcur[(np * 16 + b_row) * VPH + hk + kq * 16 + b_col8]);
#pragma unroll
                for (int nt = 0; nt < 8; nt++)
                    mma16(Of[nt], a0, a1, a2, a3, vb[nt][0], vb[nt][1]);
            }
        }
        __syncthreads();
    }

    const int b = bh >> 4, h = bh & 15;
    const float inv0 = 1.f / lrow[0], inv1 = 1.f / lrow[1];
    const int row = qt * 128 + warp * 16 + g;
#pragma unroll
    for (int nt = 0; nt < 8; nt++) {
        size_t base  = ((size_t)(b * SEQ + row))     * D_MODEL + h * 64 + nt * 8 + 2 * tt;
        size_t base2 = ((size_t)(b * SEQ + row + 8)) * D_MODEL + h * 64 + nt * 8 + 2 * tt;
        *(__half2*)&g_ctx[base]  = __floats2half2_rn(Of[nt][0] * inv0, Of[nt][1] * inv0);
        *(__half2*)&g_ctx[base2] = __floats2half2_rn(Of[nt][2] * inv1, Of[nt][3] * inv1);
    }
}

extern "C" void kernel_launch(void* const* d_in, const int* in_sizes, int n_in,
                              void* d_out, int out_size)
{
    const float* query = (const float*)d_in[0];
    const float* key   = (const float*)d_in[1];
    const float* value = (const float*)d_in[2];
    const float* Wq    = (const float*)d_in[3];
    const float* bq    = (const float*)d_in[4];
    const float* Wk    = (const float*)d_in[5];
    const float* bk    = (const float*)d_in[6];
    const float* Wv    = (const float*)d_in[7];
    const float* bv    = (const float*)d_in[8];
    const float* Wo    = (const float*)d_in[9];
    const float* bo    = (const float*)d_in[10];
    float* out = (float*)d_out;

    __half *hq, *hk, *hv, *hwq, *hwk, *hwv, *hwo, *gQ, *gK, *gV, *gC;
    cudaGetSymbolAddress((void**)&hq,  h_q);
    cudaGetSymbolAddress((void**)&hk,  h_k);
    cudaGetSymbolAddress((void**)&hv,  h_v);
    cudaGetSymbolAddress((void**)&hwq, h_wq);
    cudaGetSymbolAddress((void**)&hwk, h_wk);
    cudaGetSymbolAddress((void**)&hwv, h_wv);
    cudaGetSymbolAddress((void**)&hwo, h_wo);
    cudaGetSymbolAddress((void**)&gQ,  g_Q);
    cudaGetSymbolAddress((void**)&gK,  g_K);
    cudaGetSymbolAddress((void**)&gV,  g_V);
    cudaGetSymbolAddress((void**)&gC,  g_ctx);

    cudaFuncSetAttribute(attn_f16, cudaFuncAttributeMaxDynamicSharedMemorySize,
                         ATTN_SMEM_BYTES);
    cudaFuncSetAttribute(gemm_f16p, cudaFuncAttributeMaxDynamicSharedMemorySize,
                         GEMM_SMEM_BYTES);

    // 1) convert everything to fp16 (one launch)
    CvtJobs cj;
    cj.src[0] = query; cj.dst[0] = hq;  cj.n[0] = MTOT * D_MODEL;
    cj.src[1] = key;   cj.dst[1] = hk;  cj.n[1] = MTOT * D_MODEL;
    cj.src[2] = value; cj.dst[2] = hv;  cj.n[2] = MTOT * D_MODEL;
    cj.src[3] = Wq;    cj.dst[3] = hwq; cj.n[3] = D_MODEL * D_MODEL;
    cj.src[4] = Wk;    cj.dst[4] = hwk; cj.n[4] = D_MODEL * D_MODEL;
    cj.src[5] = Wv;    cj.dst[5] = hwv; cj.n[5] = D_MODEL * D_MODEL;
    cj.src[6] = Wo;    cj.dst[6] = hwo; cj.n[6] = D_MODEL * D_MODEL;
    cvt_f16<<<dim3(MTOT * D_MODEL / (256 * 8), 7), 256>>>(cj);

    // 2) fused Q/K/V projections
    GemmJobs3 qkv;
    qkv.j[0] = { hq, hwq, bq, gQ, 1, 0.125f * LOG2E };
    qkv.j[1] = { hk, hwk, bk, gK, 1, 1.0f };
    qkv.j[2] = { hv, hwv, bv, gV, 2, 1.0f };
    gemm_f16p<<<dim3(MTOT / 128, D_MODEL / 128, 3), 256, GEMM_SMEM_BYTES>>>(qkv);

    // 3) attention
    dim3 agrid(SEQ / 128, BATCH * NUM_HEADS);
    attn_f16<<<agrid, 256, ATTN_SMEM_BYTES>>>();

    // 4) output projection
    GemmJobs3 oj;
    oj.j[0] = { gC, hwo, bo, out, 0, 1.0f };
    oj.j[1] = oj.j[0]; oj.j[2] = oj.j[0];
    gemm_f16p<<<dim3(MTOT / 128, D_MODEL / 128, 1), 256, GEMM_SMEM_BYTES>>>(oj);
}

// round 8
// speedup vs baseline: 6.6554x; 1.0425x over previous
#include <cuda_runtime.h>
#include <cuda_fp16.h>

#define D_MODEL   1024
#define NUM_HEADS 16
#define SEQ       2048
#define BATCH     2
#define MTOT      (BATCH*SEQ)   /* 4096 */
#define LOG2E     1.4426950408889634f

// Scratch (allocation-free rule: __device__ globals).
__device__ __half h_q[(size_t)MTOT * D_MODEL];
__device__ __half h_k[(size_t)MTOT * D_MODEL];
__device__ __half h_v[(size_t)MTOT * D_MODEL];
__device__ __half h_wq[(size_t)D_MODEL * D_MODEL];
__device__ __half h_wk[(size_t)D_MODEL * D_MODEL];
__device__ __half h_wv[(size_t)D_MODEL * D_MODEL];
__device__ __half h_wo[(size_t)D_MODEL * D_MODEL];
__device__ __half g_Q[(size_t)MTOT * D_MODEL];   // [b,h,s,d], pre-scaled by 0.125*log2e
__device__ __half g_K[(size_t)MTOT * D_MODEL];   // [b,h,s,d]
__device__ __half g_V[(size_t)MTOT * D_MODEL];   // TRANSPOSED [b,h,d,s]
__device__ __half g_ctx[(size_t)MTOT * D_MODEL]; // [m, D_MODEL] fp16

__device__ __forceinline__ void ldsm4(unsigned& r0, unsigned& r1, unsigned& r2, unsigned& r3,
                                      const void* p) {
    unsigned a = (unsigned)__cvta_generic_to_shared(p);
    asm volatile("ldmatrix.sync.aligned.m8n8.x4.shared.b16 {%0,%1,%2,%3}, [%4];"
                 : "=r"(r0), "=r"(r1), "=r"(r2), "=r"(r3) : "r"(a));
}
__device__ __forceinline__ void mma16(float* c, unsigned a0, unsigned a1, unsigned a2, unsigned a3,
                                      unsigned b0, unsigned b1) {
    asm volatile("mma.sync.aligned.m16n8k16.row.col.f32.f16.f16.f32 "
                 "{%0,%1,%2,%3},{%4,%5,%6,%7},{%8,%9},{%0,%1,%2,%3};"
                 : "+f"(c[0]), "+f"(c[1]), "+f"(c[2]), "+f"(c[3])
                 : "r"(a0), "r"(a1), "r"(a2), "r"(a3), "r"(b0), "r"(b1));
}
__device__ __forceinline__ void cp16(void* smem_dst, const void* gsrc) {
    unsigned d = (unsigned)__cvta_generic_to_shared(smem_dst);
    asm volatile("cp.async.cg.shared.global [%0], [%1], 16;\n" :: "r"(d), "l"(gsrc));
}
__device__ __forceinline__ void cp_commit() { asm volatile("cp.async.commit_group;\n"); }
template <int N> __device__ __forceinline__ void cp_wait() {
    asm volatile("cp.async.wait_group %0;\n" :: "n"(N));
}

// ------------------------- fp32 -> fp16 conversion (7 tensors, one launch) ----
struct CvtJobs { const float* src[7]; __half* dst[7]; int n[7]; };

__global__ __launch_bounds__(256) void cvt_f16(CvtJobs jobs)
{
    int j = blockIdx.y;
    int base = (blockIdx.x * 256 + threadIdx.x) * 8;
    if (base >= jobs.n[j]) return;
    const float4* s = (const float4*)(jobs.src[j] + base);
    float4 v0 = s[0], v1 = s[1];
    __half2 p0 = __floats2half2_rn(v0.x, v0.y);
    __half2 p1 = __floats2half2_rn(v0.z, v0.w);
    __half2 p2 = __floats2half2_rn(v1.x, v1.y);
    __half2 p3 = __floats2half2_rn(v1.z, v1.w);
    uint4 u; u.x = *(unsigned*)&p0; u.y = *(unsigned*)&p1;
    u.z = *(unsigned*)&p2; u.w = *(unsigned*)&p3;
    *(uint4*)(jobs.dst[j] + base) = u;
}

// ------------------------- fp16 GEMM, 4-stage cp.async pipeline ----------------
// C = A * W^T + bias. A:[M,1024] fp16, W:[1024,1024] fp16 (row n = output col).
// mode 0: fp32 [m,n]; mode 1: fp16 headsplit [b,h,s,d] (*oscale);
// mode 2: fp16 headsplit TRANSPOSED [b,h,d,s]
#define KGP 40         /* smem pitch halves: 32 + 8 pad */
#define GSTG (128 * KGP)            /* halves per matrix per stage: 5120 */
#define GSTAGE_H (2 * GSTG)         /* A+B per stage: 10240 halves */
#define NSTAGE 4
#define GEMM_SMEM_BYTES (NSTAGE * GSTAGE_H * 2)   /* 81920 */

struct GemmJob { const __half* A; const __half* W; const float* bias;
                 void* C; int mode; float oscale; };
struct GemmJobs3 { GemmJob j[3]; };

__global__ __launch_bounds__(256, 2) void gemm_f16p(GemmJobs3 js)
{
    extern __shared__ __half sg[];
    const GemmJob jb = js.j[blockIdx.z];
    const int t = threadIdx.x, lane = t & 31, warp = t >> 5;
    const int wm = warp >> 1, wn = warp & 1;
    const int g = lane >> 2, tt = lane & 3;
    const int bm = blockIdx.x, bn = blockIdx.y;

    float acc[2][8][4];
#pragma unroll
    for (int mt = 0; mt < 2; mt++)
#pragma unroll
        for (int nt = 0; nt < 8; nt++)
#pragma unroll
            for (int i = 0; i < 4; i++) acc[mt][nt][i] = 0.f;

    const __half* Ap = jb.A + (size_t)bm * 128 * 1024;
    const __half* Wp = jb.W + (size_t)bn * 128 * 1024;

    const int a_row  = (lane & 7) + ((lane & 8) ? 8 : 0);
    const int a_col8 = (lane & 16) ? 8 : 0;
    const int b_row  = (lane & 7) + ((lane & 16) ? 8 : 0);
    const int b_col8 = (lane & 8) ? 8 : 0;

    const int fm0 = t >> 2, fc0 = (t & 3) * 8;
    const int fm1 = (t + 256) >> 2, fc1 = ((t + 256) & 3) * 8;

    // prologue: stages 0..2
#pragma unroll
    for (int st = 0; st < 3; st++) {
        __half* Sa = sg + st * GSTAGE_H;
        __half* Sb = Sa + GSTG;
        int k0 = st * 32;
        cp16(&Sa[fm0 * KGP + fc0], Ap + (size_t)fm0 * 1024 + k0 + fc0);
        cp16(&Sa[fm1 * KGP + fc1], Ap + (size_t)fm1 * 1024 + k0 + fc1);
        cp16(&Sb[fm0 * KGP + fc0], Wp + (size_t)fm0 * 1024 + k0 + fc0);
        cp16(&Sb[fm1 * KGP + fc1], Wp + (size_t)fm1 * 1024 + k0 + fc1);
        cp_commit();
    }

    for (int ks = 0; ks < 32; ks++) {
        cp_wait<2>();          // stage ks resident; ks+1, ks+2 in flight
        __syncthreads();       // also protects buffer (ks+3)&3 (= compute of ks-1)

        if (ks + 3 < 32) {
            int st = (ks + 3) & 3;
            __half* Sa = sg + st * GSTAGE_H;
            __half* Sb = Sa + GSTG;
            int k0 = (ks + 3) * 32;
            cp16(&Sa[fm0 * KGP + fc0], Ap + (size_t)fm0 * 1024 + k0 + fc0);
            cp16(&Sa[fm1 * KGP + fc1], Ap + (size_t)fm1 * 1024 + k0 + fc1);
            cp16(&Sb[fm0 * KGP + fc0], Wp + (size_t)fm0 * 1024 + k0 + fc0);
            cp16(&Sb[fm1 * KGP + fc1], Wp + (size_t)fm1 * 1024 + k0 + fc1);
        }
        cp_commit();           // empty-group commit keeps accounting uniform

        __half* Sa = sg + (ks & 3) * GSTAGE_H;
        __half* Sb = Sa + GSTG;
#pragma unroll
        for (int kq = 0; kq < 32; kq += 16) {
            unsigned a[2][4];
#pragma unroll
            for (int mt = 0; mt < 2; mt++) {
                int base = wm * 32 + mt * 16;
                ldsm4(a[mt][0], a[mt][1], a[mt][2], a[mt][3],
                      &Sa[(base + a_row) * KGP + kq + a_col8]);
            }
            unsigned b[8][2];
#pragma unroll
            for (int np = 0; np < 4; np++) {
                int nb = wn * 64 + np * 16;
                ldsm4(b[np * 2][0], b[np * 2][1], b[np * 2 + 1][0], b[np * 2 + 1][1],
                      &Sb[(nb + b_row) * KGP + kq + b_col8]);
            }
#pragma unroll
            for (int mt = 0; mt < 2; mt++)
#pragma unroll
                for (int nt = 0; nt < 8; nt++)
                    mma16(acc[mt][nt], a[mt][0], a[mt][1], a[mt][2], a[mt][3],
                          b[nt][0], b[nt][1]);
        }
    }

#pragma unroll
    for (int mt = 0; mt < 2; mt++) {
        int row0 = bm * 128 + wm * 32 + mt * 16 + g;
#pragma unroll
        for (int nt = 0; nt < 8; nt++) {
            int cc = bn * 128 + wn * 64 + nt * 8 + 2 * tt;
            float2 bb = *(const float2*)&jb.bias[cc];
#pragma unroll
            for (int rp = 0; rp < 2; rp++) {
                int row = row0 + rp * 8;
                float2 v;
                v.x = acc[mt][nt][rp * 2 + 0] + bb.x;
                v.y = acc[mt][nt][rp * 2 + 1] + bb.y;
                int b = row >> 11, sq = row & (SEQ - 1);
                int h = cc >> 6, dd = cc & 63;
                if (jb.mode == 1) {
                    __half* C = (__half*)jb.C;
                    __half2 hv = __floats2half2_rn(v.x * jb.oscale, v.y * jb.oscale);
                    *(__half2*)&C[((size_t)((b * NUM_HEADS + h) * SEQ + sq) << 6) + dd] = hv;
                } else if (jb.mode == 2) {
                    __half* C = (__half*)jb.C;
                    size_t base = (size_t)((b * NUM_HEADS + h) * 64 + dd) * SEQ + sq;
                    C[base] = __float2half_rn(v.x);
                    C[base + SEQ] = __float2half_rn(v.y);
                } else {
                    float* C = (float*)jb.C;
                    *(float2*)&C[(size_t)row * D_MODEL + cc] = v;
                }
            }
        }
    }
}

// ------------------------- flash attention, fp16 mma -------------------------
// 128 threads (4 warps), Br=64, 2 CTAs/SM. Key tiles of 128, double buffered.
#define KPH 72
#define VPH 136
#define PPH 72
#define KS_H (128 * KPH)
#define VT_H (64 * VPH)
#define P_H  (16 * PPH)
#define ATTN_SMEM_BYTES ((2 * KS_H + 2 * VT_H + 4 * P_H) * 2)  /* 80896 */

__global__ __launch_bounds__(128, 2) void attn_f16()
{
    extern __shared__ __half smh[];
    __half* const Ksm0 = smh;
    __half* const Ksm1 = smh + KS_H;
    __half* const Vsm0 = smh + 2 * KS_H;
    __half* const Vsm1 = smh + 2 * KS_H + VT_H;

    const int t = threadIdx.x, lane = t & 31, warp = t >> 5;
    const int g = lane >> 2, tt = lane & 3;
    const int qt = blockIdx.x;   // 0..31 (q tiles of 64)
    const int bh = blockIdx.y;

    __half* const Pw = smh + 2 * KS_H + 2 * VT_H + warp * P_H;

    const __half* Qb  = g_Q + ((size_t)bh * SEQ + qt * 64) * 64;
    const __half* Kb  = g_K + (size_t)bh * SEQ * 64;
    const __half* Vtb = g_V + (size_t)bh * 64 * SEQ;

    unsigned Qf[4][4];
    const int qr = warp * 16;
#pragma unroll
    for (int dq = 0; dq < 4; dq++) {
        Qf[dq][0] = *(const unsigned*)(Qb + (qr + g)     * 64 + dq * 16 + 2 * tt);
        Qf[dq][1] = *(const unsigned*)(Qb + (qr + g + 8) * 64 + dq * 16 + 2 * tt);
        Qf[dq][2] = *(const unsigned*)(Qb + (qr + g)     * 64 + dq * 16 + 8 + 2 * tt);
        Qf[dq][3] = *(const unsigned*)(Qb + (qr + g + 8) * 64 + dq * 16 + 8 + 2 * tt);
    }

    float Of[8][4];
#pragma unroll
    for (int nt = 0; nt < 8; nt++)
#pragma unroll
        for (int i = 0; i < 4; i++) Of[nt][i] = 0.f;
    float mrow[2] = {-1e30f, -1e30f};
    float lrow[2] = {0.f, 0.f};

    const int a_row  = (lane & 7) + ((lane & 8) ? 8 : 0);
    const int a_col8 = (lane & 16) ? 8 : 0;
    const int b_row  = (lane & 7) + ((lane & 16) ? 8 : 0);
    const int b_col8 = (lane & 8) ? 8 : 0;

    // prologue fill: 8 K cps + 8 V cps per thread (128 threads)
    {
#pragma unroll
        for (int l = 0; l < 8; l++) {
            int s = t + 128 * l;          // 0..1023
            int kr = s >> 3, kc = (s & 7) * 8;
            cp16(&Ksm0[kr * KPH + kc], Kb + (size_t)kr * 64 + kc);
            int vr = s >> 4, vc = (s & 15) * 8;
            cp16(&Vsm0[vr * VPH + vc], Vtb + (size_t)vr * SEQ + vc);
        }
        cp_commit();
    }

    for (int kt = 0; kt < SEQ / 128; kt++) {
        __half* const Kcur = (kt & 1) ? Ksm1 : Ksm0;
        __half* const Vcur = (kt & 1) ? Vsm1 : Vsm0;
        __half* const Knxt = (kt & 1) ? Ksm0 : Ksm1;
        __half* const Vnxt = (kt & 1) ? Vsm0 : Vsm1;

        cp_wait<0>();
        __syncthreads();

        if (kt < SEQ / 128 - 1) {
            const __half* Kp = Kb + (size_t)(kt + 1) * 128 * 64;
            const __half* Vp = Vtb + (kt + 1) * 128;
#pragma unroll
            for (int l = 0; l < 8; l++) {
                int s = t + 128 * l;
                int kr = s >> 3, kc = (s & 7) * 8;
                cp16(&Knxt[kr * KPH + kc], Kp + (size_t)kr * 64 + kc);
                int vr = s >> 4, vc = (s & 15) * 8;
                cp16(&Vnxt[vr * VPH + vc], Vp + (size_t)vr * SEQ + vc);
            }
            cp_commit();
        }

#pragma unroll
        for (int hf = 0; hf < 2; hf++) {
            const int hk = hf * 64;

            float sf[8][4];
#pragma unroll
            for (int nt = 0; nt < 8; nt++)
#pragma unroll
                for (int i = 0; i < 4; i++) sf[nt][i] = 0.f;

#pragma unroll
            for (int dq = 0; dq < 4; dq++) {
                unsigned b[8][2];
#pragma unroll
                for (int np = 0; np < 4; np++)
                    ldsm4(b[np * 2][0], b[np * 2][1], b[np * 2 + 1][0], b[np * 2 + 1][1],
                          &Kcur[(hk + np * 16 + b_row) * KPH + dq * 16 + b_col8]);
#pragma unroll
                for (int nt = 0; nt < 8; nt++)
                    mma16(sf[nt], Qf[dq][0], Qf[dq][1], Qf[dq][2], Qf[dq][3],
                          b[nt][0], b[nt][1]);
            }

            float alpha[2];
#pragma unroll
            for (int rp = 0; rp < 2; rp++) {
                float mx = -1e30f;
#pragma unroll
                for (int nt = 0; nt < 8; nt++)
                    mx = fmaxf(mx, fmaxf(sf[nt][rp * 2], sf[nt][rp * 2 + 1]));
                mx = fmaxf(mx, __shfl_xor_sync(0xffffffffu, mx, 1));
                mx = fmaxf(mx, __shfl_xor_sync(0xffffffffu, mx, 2));
                float nm = fmaxf(mrow[rp], mx);
                float sum = 0.f;
#pragma unroll
                for (int nt = 0; nt < 8; nt++) {
                    float p0 = exp2f(sf[nt][rp * 2]     - nm);
                    float p1 = exp2f(sf[nt][rp * 2 + 1] - nm);
                    sf[nt][rp * 2] = p0; sf[nt][rp * 2 + 1] = p1;
                    sum += p0 + p1;
                }
                sum += __shfl_xor_sync(0xffffffffu, sum, 1);
                sum += __shfl_xor_sync(0xffffffffu, sum, 2);
                alpha[rp] = exp2f(mrow[rp] - nm);
                mrow[rp] = nm;
                lrow[rp] = lrow[rp] * alpha[rp] + sum;
            }
#pragma unroll
            for (int nt = 0; nt < 8; nt++) {
                Of[nt][0] *= alpha[0]; Of[nt][1] *= alpha[0];
                Of[nt][2] *= alpha[1]; Of[nt][3] *= alpha[1];
            }

            __syncwarp();
#pragma unroll
            for (int nt = 0; nt < 8; nt++) {
                __half2 h0 = __floats2half2_rn(sf[nt][0], sf[nt][1]);
                __half2 h1 = __floats2half2_rn(sf[nt][2], sf[nt][3]);
                *(__half2*)&Pw[g       * PPH + nt * 8 + 2 * tt] = h0;
                *(__half2*)&Pw[(g + 8) * PPH + nt * 8 + 2 * tt] = h1;
            }
            __syncwarp();

#pragma unroll
            for (int kq = 0; kq < 4; kq++) {
                unsigned a0, a1, a2, a3;
                ldsm4(a0, a1, a2, a3, &Pw[a_row * PPH + kq * 16 + a_col8]);
                unsigned vb[8][2];
#pragma unroll
                for (int np = 0; np < 4; np++)
                    ldsm4(vb[np * 2][0], vb[np * 2][1], vb[np * 2 + 1][0], vb[np * 2 + 1][1],
                          &Vcur[(np * 16 + b_row) * VPH + hk + kq * 16 + b_col8]);
#pragma unroll
                for (int nt = 0; nt < 8; nt++)
                    mma16(Of[nt], a0, a1, a2, a3, vb[nt][0], vb[nt][1]);
            }
        }
        __syncthreads();
    }

    const int b = bh >> 4, h = bh & 15;
    const float inv0 = 1.f / lrow[0], inv1 = 1.f / lrow[1];
    const int row = qt * 64 + warp * 16 + g;
#pragma unroll
    for (int nt = 0; nt < 8; nt++) {
        size_t base  = ((size_t)(b * SEQ + row))     * D_MODEL + h * 64 + nt * 8 + 2 * tt;
        size_t base2 = ((size_t)(b * SEQ + row + 8)) * D_MODEL + h * 64 + nt * 8 + 2 * tt;
        *(__half2*)&g_ctx[base]  = __floats2half2_rn(Of[nt][0] * inv0, Of[nt][1] * inv0);
        *(__half2*)&g_ctx[base2] = __floats2half2_rn(Of[nt][2] * inv1, Of[nt][3] * inv1);
    }
}

extern "C" void kernel_launch(void* const* d_in, const int* in_sizes, int n_in,
                              void* d_out, int out_size)
{
    const float* query = (const float*)d_in[0];
    const float* key   = (const float*)d_in[1];
    const float* value = (const float*)d_in[2];
    const float* Wq    = (const float*)d_in[3];
    const float* bq    = (const float*)d_in[4];
    const float* Wk    = (const float*)d_in[5];
    const float* bk    = (const float*)d_in[6];
    const float* Wv    = (const float*)d_in[7];
    const float* bv    = (const float*)d_in[8];
    const float* Wo    = (const float*)d_in[9];
    const float* bo    = (const float*)d_in[10];
    float* out = (float*)d_out;

    __half *hq, *hk, *hv, *hwq, *hwk, *hwv, *hwo, *gQ, *gK, *gV, *gC;
    cudaGetSymbolAddress((void**)&hq,  h_q);
    cudaGetSymbolAddress((void**)&hk,  h_k);
    cudaGetSymbolAddress((void**)&hv,  h_v);
    cudaGetSymbolAddress((void**)&hwq, h_wq);
    cudaGetSymbolAddress((void**)&hwk, h_wk);
    cudaGetSymbolAddress((void**)&hwv, h_wv);
    cudaGetSymbolAddress((void**)&hwo, h_wo);
    cudaGetSymbolAddress((void**)&gQ,  g_Q);
    cudaGetSymbolAddress((void**)&gK,  g_K);
    cudaGetSymbolAddress((void**)&gV,  g_V);
    cudaGetSymbolAddress((void**)&gC,  g_ctx);

    cudaFuncSetAttribute(attn_f16, cudaFuncAttributeMaxDynamicSharedMemorySize,
                         ATTN_SMEM_BYTES);
    cudaFuncSetAttribute(gemm_f16p, cudaFuncAttributeMaxDynamicSharedMemorySize,
                         GEMM_SMEM_BYTES);

    // 1) convert everything to fp16 (one launch)
    CvtJobs cj;
    cj.src[0] = query; cj.dst[0] = hq;  cj.n[0] = MTOT * D_MODEL;
    cj.src[1] = key;   cj.dst[1] = hk;  cj.n[1] = MTOT * D_MODEL;
    cj.src[2] = value; cj.dst[2] = hv;  cj.n[2] = MTOT * D_MODEL;
    cj.src[3] = Wq;    cj.dst[3] = hwq; cj.n[3] = D_MODEL * D_MODEL;
    cj.src[4] = Wk;    cj.dst[4] = hwk; cj.n[4] = D_MODEL * D_MODEL;
    cj.src[5] = Wv;    cj.dst[5] = hwv; cj.n[5] = D_MODEL * D_MODEL;
    cj.src[6] = Wo;    cj.dst[6] = hwo; cj.n[6] = D_MODEL * D_MODEL;
    cvt_f16<<<dim3(MTOT * D_MODEL / (256 * 8), 7), 256>>>(cj);

    // 2) fused Q/K/V projections
    GemmJobs3 qkv;
    qkv.j[0] = { hq, hwq, bq, gQ, 1, 0.125f * LOG2E };
    qkv.j[1] = { hk, hwk, bk, gK, 1, 1.0f };
    qkv.j[2] = { hv, hwv, bv, gV, 2, 1.0f };
    gemm_f16p<<<dim3(MTOT / 128, D_MODEL / 128, 3), 256, GEMM_SMEM_BYTES>>>(qkv);

    // 3) attention
    dim3 agrid(SEQ / 64, BATCH * NUM_HEADS);
    attn_f16<<<agrid, 128, ATTN_SMEM_BYTES>>>();

    // 4) output projection
    GemmJobs3 oj;
    oj.j[0] = { gC, hwo, bo, out, 0, 1.0f };
    oj.j[1] = oj.j[0]; oj.j[2] = oj.j[0];
    gemm_f16p<<<dim3(MTOT / 128, D_MODEL / 128, 1), 256, GEMM_SMEM_BYTES>>>(oj);
}

// round 11
// speedup vs baseline: 7.1402x; 1.0728x over previous
#include <cuda_runtime.h>
#include <cuda_fp16.h>
#include <cstdint>

#define D_MODEL   1024
#define NUM_HEADS 16
#define SEQ       2048
#define BATCH     2
#define MTOT      (BATCH*SEQ)   /* 4096 */
#define LOG2E     1.4426950408889634f

// Scratch (allocation-free rule: __device__ globals).
__device__ __half h_q[(size_t)MTOT * D_MODEL];
__device__ __half h_k[(size_t)MTOT * D_MODEL];
__device__ __half h_v[(size_t)MTOT * D_MODEL];
__device__ __half h_wq[(size_t)D_MODEL * D_MODEL];
__device__ __half h_wk[(size_t)D_MODEL * D_MODEL];
__device__ __half h_wv[(size_t)D_MODEL * D_MODEL];
__device__ __half h_wo[(size_t)D_MODEL * D_MODEL];
__device__ __half g_Q[(size_t)MTOT * D_MODEL];   // [b,h,s,d], pre-scaled by 0.125*log2e
__device__ __half g_K[(size_t)MTOT * D_MODEL];   // [b,h,s,d]
__device__ __half g_V[(size_t)MTOT * D_MODEL];   // TRANSPOSED [b,h,d,s]
__device__ __half g_ctx[(size_t)MTOT * D_MODEL]; // [m, D_MODEL] fp16

__device__ __forceinline__ void ldsm4(unsigned& r0, unsigned& r1, unsigned& r2, unsigned& r3,
                                      const void* p) {
    unsigned a = (unsigned)__cvta_generic_to_shared(p);
    asm volatile("ldmatrix.sync.aligned.m8n8.x4.shared.b16 {%0,%1,%2,%3}, [%4];"
                 : "=r"(r0), "=r"(r1), "=r"(r2), "=r"(r3) : "r"(a));
}
__device__ __forceinline__ void mma16(float* c, unsigned a0, unsigned a1, unsigned a2, unsigned a3,
                                      unsigned b0, unsigned b1) {
    asm volatile("mma.sync.aligned.m16n8k16.row.col.f32.f16.f16.f32 "
                 "{%0,%1,%2,%3},{%4,%5,%6,%7},{%8,%9},{%0,%1,%2,%3};"
                 : "+f"(c[0]), "+f"(c[1]), "+f"(c[2]), "+f"(c[3])
                 : "r"(a0), "r"(a1), "r"(a2), "r"(a3), "r"(b0), "r"(b1));
}
__device__ __forceinline__ void cp16(void* smem_dst, const void* gsrc) {
    unsigned d = (unsigned)__cvta_generic_to_shared(smem_dst);
    asm volatile("cp.async.cg.shared.global [%0], [%1], 16;\n" :: "r"(d), "l"(gsrc));
}
__device__ __forceinline__ void cp_commit() { asm volatile("cp.async.commit_group;\n"); }
template <int N> __device__ __forceinline__ void cp_wait() {
    asm volatile("cp.async.wait_group %0;\n" :: "n"(N));
}

// ------------------------- fp32 -> fp16 conversion (7 tensors, one launch) ----
struct CvtJobs { const float* src[7]; __half* dst[7]; int n[7]; };

__global__ __launch_bounds__(256) void cvt_f16(CvtJobs jobs)
{
    int j = blockIdx.y;
    int base = (blockIdx.x * 256 + threadIdx.x) * 8;
    if (base >= jobs.n[j]) return;
    const float4* s = (const float4*)(jobs.src[j] + base);
    float4 v0 = s[0], v1 = s[1];
    __half2 p0 = __floats2half2_rn(v0.x, v0.y);
    __half2 p1 = __floats2half2_rn(v0.z, v0.w);
    __half2 p2 = __floats2half2_rn(v1.x, v1.y);
    __half2 p3 = __floats2half2_rn(v1.z, v1.w);
    uint4 u; u.x = *(unsigned*)&p0; u.y = *(unsigned*)&p1;
    u.z = *(unsigned*)&p2; u.w = *(unsigned*)&p3;
    *(uint4*)(jobs.dst[j] + base) = u;
}

// ------------------------- fp16 GEMM, 4-stage cp.async pipeline ----------------
#define KGP 40
#define GSTG (128 * KGP)
#define GSTAGE_H (2 * GSTG)
#define NSTAGE 4
#define GEMM_SMEM_BYTES (NSTAGE * GSTAGE_H * 2)   /* 81920 */

struct GemmJob { const __half* A; const __half* W; const float* bias;
                 void* C; int mode; float oscale; };
struct GemmJobs3 { GemmJob j[3]; };

__global__ __launch_bounds__(256, 2) void gemm_f16p(GemmJobs3 js)
{
    extern __shared__ __half sg[];
    const GemmJob jb = js.j[blockIdx.z];
    const int t = threadIdx.x, lane = t & 31, warp = t >> 5;
    const int wm = warp >> 1, wn = warp & 1;
    const int g = lane >> 2, tt = lane & 3;
    const int bm = blockIdx.x, bn = blockIdx.y;

    float acc[2][8][4];
#pragma unroll
    for (int mt = 0; mt < 2; mt++)
#pragma unroll
        for (int nt = 0; nt < 8; nt++)
#pragma unroll
            for (int i = 0; i < 4; i++) acc[mt][nt][i] = 0.f;

    const __half* Ap = jb.A + (size_t)bm * 128 * 1024;
    const __half* Wp = jb.W + (size_t)bn * 128 * 1024;

    const int a_row  = (lane & 7) + ((lane & 8) ? 8 : 0);
    const int a_col8 = (lane & 16) ? 8 : 0;
    const int b_row  = (lane & 7) + ((lane & 16) ? 8 : 0);
    const int b_col8 = (lane & 8) ? 8 : 0;

    const int fm0 = t >> 2, fc0 = (t & 3) * 8;
    const int fm1 = (t + 256) >> 2, fc1 = ((t + 256) & 3) * 8;

#pragma unroll
    for (int st = 0; st < 3; st++) {
        __half* Sa = sg + st * GSTAGE_H;
        __half* Sb = Sa + GSTG;
        int k0 = st * 32;
        cp16(&Sa[fm0 * KGP + fc0], Ap + (size_t)fm0 * 1024 + k0 + fc0);
        cp16(&Sa[fm1 * KGP + fc1], Ap + (size_t)fm1 * 1024 + k0 + fc1);
        cp16(&Sb[fm0 * KGP + fc0], Wp + (size_t)fm0 * 1024 + k0 + fc0);
        cp16(&Sb[fm1 * KGP + fc1], Wp + (size_t)fm1 * 1024 + k0 + fc1);
        cp_commit();
    }

    for (int ks = 0; ks < 32; ks++) {
        cp_wait<2>();
        __syncthreads();

        if (ks + 3 < 32) {
            int st = (ks + 3) & 3;
            __half* Sa = sg + st * GSTAGE_H;
            __half* Sb = Sa + GSTG;
            int k0 = (ks + 3) * 32;
            cp16(&Sa[fm0 * KGP + fc0], Ap + (size_t)fm0 * 1024 + k0 + fc0);
            cp16(&Sa[fm1 * KGP + fc1], Ap + (size_t)fm1 * 1024 + k0 + fc1);
            cp16(&Sb[fm0 * KGP + fc0], Wp + (size_t)fm0 * 1024 + k0 + fc0);
            cp16(&Sb[fm1 * KGP + fc1], Wp + (size_t)fm1 * 1024 + k0 + fc1);
        }
        cp_commit();

        __half* Sa = sg + (ks & 3) * GSTAGE_H;
        __half* Sb = Sa + GSTG;
#pragma unroll
        for (int kq = 0; kq < 32; kq += 16) {
            unsigned a[2][4];
#pragma unroll
            for (int mt = 0; mt < 2; mt++) {
                int base = wm * 32 + mt * 16;
                ldsm4(a[mt][0], a[mt][1], a[mt][2], a[mt][3],
                      &Sa[(base + a_row) * KGP + kq + a_col8]);
            }
            unsigned b[8][2];
#pragma unroll
            for (int np = 0; np < 4; np++) {
                int nb = wn * 64 + np * 16;
                ldsm4(b[np * 2][0], b[np * 2][1], b[np * 2 + 1][0], b[np * 2 + 1][1],
                      &Sb[(nb + b_row) * KGP + kq + b_col8]);
            }
#pragma unroll
            for (int mt = 0; mt < 2; mt++)
#pragma unroll
                for (int nt = 0; nt < 8; nt++)
                    mma16(acc[mt][nt], a[mt][0], a[mt][1], a[mt][2], a[mt][3],
                          b[nt][0], b[nt][1]);
        }
    }

#pragma unroll
    for (int mt = 0; mt < 2; mt++) {
        int row0 = bm * 128 + wm * 32 + mt * 16 + g;
#pragma unroll
        for (int nt = 0; nt < 8; nt++) {
            int cc = bn * 128 + wn * 64 + nt * 8 + 2 * tt;
            float2 bb = *(const float2*)&jb.bias[cc];
#pragma unroll
            for (int rp = 0; rp < 2; rp++) {
                int row = row0 + rp * 8;
                float2 v;
                v.x = acc[mt][nt][rp * 2 + 0] + bb.x;
                v.y = acc[mt][nt][rp * 2 + 1] + bb.y;
                int b = row >> 11, sq = row & (SEQ - 1);
                int h = cc >> 6, dd = cc & 63;
                if (jb.mode == 1) {
                    __half* C = (__half*)jb.C;
                    __half2 hv = __floats2half2_rn(v.x * jb.oscale, v.y * jb.oscale);
                    *(__half2*)&C[((size_t)((b * NUM_HEADS + h) * SEQ + sq) << 6) + dd] = hv;
                } else if (jb.mode == 2) {
                    __half* C = (__half*)jb.C;
                    size_t base = (size_t)((b * NUM_HEADS + h) * 64 + dd) * SEQ + sq;
                    C[base] = __float2half_rn(v.x);
                    C[base + SEQ] = __float2half_rn(v.y);
                } else {
                    float* C = (float*)jb.C;
                    *(float2*)&C[(size_t)row * D_MODEL + cc] = v;
                }
            }
        }
    }
}

// ------------------------- flash attention, fp16 mma -------------------------
// 128 threads (4 warps), warp owns 32 q rows (2 m-frags) -> Br=128, 2 CTAs/SM.
// Key tiles of 128, double buffered via cp.async. K/V LDSM bytes per MAC halved.
#define KPH 72
#define VPH 136
#define PPH 72
#define KS_H (128 * KPH)
#define VT_H (64 * VPH)
#define P_H  (32 * PPH)
#define ATTN_SMEM_BYTES ((2 * KS_H + 2 * VT_H + 4 * P_H) * 2)  /* 90112 */

__global__ __launch_bounds__(128, 2) void attn_f16()
{
    extern __shared__ __half smh[];
    __half* const Ksm0 = smh;
    __half* const Ksm1 = smh + KS_H;
    __half* const Vsm0 = smh + 2 * KS_H;
    __half* const Vsm1 = smh + 2 * KS_H + VT_H;

    const int t = threadIdx.x, lane = t & 31, warp = t >> 5;
    const int g = lane >> 2, tt = lane & 3;
    const int qt = blockIdx.x;   // 0..15 (q tiles of 128)
    const int bh = blockIdx.y;

    __half* const Pw = smh + 2 * KS_H + 2 * VT_H + warp * P_H;

    const __half* Qb  = g_Q + ((size_t)bh * SEQ + qt * 128) * 64;
    const __half* Kb  = g_K + (size_t)bh * SEQ * 64;
    const __half* Vtb = g_V + (size_t)bh * 64 * SEQ;

    // Q A-fragments: 2 m-frags x 4 k-steps (scale folded into g_Q)
    unsigned Qf[4][2][4];
    const int qr = warp * 32;
#pragma unroll
    for (int dq = 0; dq < 4; dq++)
#pragma unroll
        for (int mt = 0; mt < 2; mt++) {
            int r0 = qr + mt * 16 + g;
            Qf[dq][mt][0] = *(const unsigned*)(Qb + r0       * 64 + dq * 16 + 2 * tt);
            Qf[dq][mt][1] = *(const unsigned*)(Qb + (r0 + 8) * 64 + dq * 16 + 2 * tt);
            Qf[dq][mt][2] = *(const unsigned*)(Qb + r0       * 64 + dq * 16 + 8 + 2 * tt);
            Qf[dq][mt][3] = *(const unsigned*)(Qb + (r0 + 8) * 64 + dq * 16 + 8 + 2 * tt);
        }

    float Of[2][8][4];
#pragma unroll
    for (int mt = 0; mt < 2; mt++)
#pragma unroll
        for (int nt = 0; nt < 8; nt++)
#pragma unroll
            for (int i = 0; i < 4; i++) Of[mt][nt][i] = 0.f;
    float mrow[2][2] = {{-1e30f, -1e30f}, {-1e30f, -1e30f}};
    float lrow[2][2] = {{0.f, 0.f}, {0.f, 0.f}};

    const int a_row  = (lane & 7) + ((lane & 8) ? 8 : 0);
    const int a_col8 = (lane & 16) ? 8 : 0;
    const int b_row  = (lane & 7) + ((lane & 16) ? 8 : 0);
    const int b_col8 = (lane & 8) ? 8 : 0;

    {
#pragma unroll
        for (int l = 0; l < 8; l++) {
            int s = t + 128 * l;
            int kr = s >> 3, kc = (s & 7) * 8;
            cp16(&Ksm0[kr * KPH + kc], Kb + (size_t)kr * 64 + kc);
            int vr = s >> 4, vc = (s & 15) * 8;
            cp16(&Vsm0[vr * VPH + vc], Vtb + (size_t)vr * SEQ + vc);
        }
        cp_commit();
    }

    for (int kt = 0; kt < SEQ / 128; kt++) {
        __half* const Kcur = (kt & 1) ? Ksm1 : Ksm0;
        __half* const Vcur = (kt & 1) ? Vsm1 : Vsm0;
        __half* const Knxt = (kt & 1) ? Ksm0 : Ksm1;
        __half* const Vnxt = (kt & 1) ? Vsm0 : Vsm1;

        cp_wait<0>();
        __syncthreads();

        if (kt < SEQ / 128 - 1) {
            const __half* Kp = Kb + (size_t)(kt + 1) * 128 * 64;
            const __half* Vp = Vtb + (kt + 1) * 128;
#pragma unroll
            for (int l = 0; l < 8; l++) {
                int s = t + 128 * l;
                int kr = s >> 3, kc = (s & 7) * 8;
                cp16(&Knxt[kr * KPH + kc], Kp + (size_t)kr * 64 + kc);
                int vr = s >> 4, vc = (s & 15) * 8;
                cp16(&Vnxt[vr * VPH + vc], Vp + (size_t)vr * SEQ + vc);
            }
            cp_commit();
        }

#pragma unroll
        for (int hf = 0; hf < 2; hf++) {
            const int hk = hf * 64;

            // ---- S = Q K^T for 32 q rows x 64 keys ----
            float sf[2][8][4];
#pragma unroll
            for (int mt = 0; mt < 2; mt++)
#pragma unroll
                for (int nt = 0; nt < 8; nt++)
#pragma unroll
                    for (int i = 0; i < 4; i++) sf[mt][nt][i] = 0.f;

#pragma unroll
            for (int dq = 0; dq < 4; dq++) {
                unsigned b[8][2];
#pragma unroll
                for (int np = 0; np < 4; np++)
                    ldsm4(b[np * 2][0], b[np * 2][1], b[np * 2 + 1][0], b[np * 2 + 1][1],
                          &Kcur[(hk + np * 16 + b_row) * KPH + dq * 16 + b_col8]);
#pragma unroll
                for (int mt = 0; mt < 2; mt++)
#pragma unroll
                    for (int nt = 0; nt < 8; nt++)
                        mma16(sf[mt][nt], Qf[dq][mt][0], Qf[dq][mt][1],
                              Qf[dq][mt][2], Qf[dq][mt][3], b[nt][0], b[nt][1]);
            }

            // ---- online softmax (exp2 domain), rows mt*16+{g, g+8} ----
#pragma unroll
            for (int mt = 0; mt < 2; mt++) {
                float alpha[2];
#pragma unroll
                for (int rp = 0; rp < 2; rp++) {
                    float mx = -1e30f;
#pragma unroll
                    for (int nt = 0; nt < 8; nt++)
                        mx = fmaxf(mx, fmaxf(sf[mt][nt][rp * 2], sf[mt][nt][rp * 2 + 1]));
                    mx = fmaxf(mx, __shfl_xor_sync(0xffffffffu, mx, 1));
                    mx = fmaxf(mx, __shfl_xor_sync(0xffffffffu, mx, 2));
                    float nm = fmaxf(mrow[mt][rp], mx);
                    float sum = 0.f;
#pragma unroll
                    for (int nt = 0; nt < 8; nt++) {
                        float p0 = exp2f(sf[mt][nt][rp * 2]     - nm);
                        float p1 = exp2f(sf[mt][nt][rp * 2 + 1] - nm);
                        sf[mt][nt][rp * 2] = p0; sf[mt][nt][rp * 2 + 1] = p1;
                        sum += p0 + p1;
                    }
                    sum += __shfl_xor_sync(0xffffffffu, sum, 1);
                    sum += __shfl_xor_sync(0xffffffffu, sum, 2);
                    alpha[rp] = exp2f(mrow[mt][rp] - nm);
                    mrow[mt][rp] = nm;
                    lrow[mt][rp] = lrow[mt][rp] * alpha[rp] + sum;
                }
#pragma unroll
                for (int nt = 0; nt < 8; nt++) {
                    Of[mt][nt][0] *= alpha[0]; Of[mt][nt][1] *= alpha[0];
                    Of[mt][nt][2] *= alpha[1]; Of[mt][nt][3] *= alpha[1];
                }
            }

            // ---- stage P (fp16) into per-warp smem (32 rows) ----
            __syncwarp();
#pragma unroll
            for (int mt = 0; mt < 2; mt++)
#pragma unroll
                for (int nt = 0; nt < 8; nt++) {
                    __half2 h0 = __floats2half2_rn(sf[mt][nt][0], sf[mt][nt][1]);
                    __half2 h1 = __floats2half2_rn(sf[mt][nt][2], sf[mt][nt][3]);
                    *(__half2*)&Pw[(mt * 16 + g)     * PPH + nt * 8 + 2 * tt] = h0;
                    *(__half2*)&Pw[(mt * 16 + g + 8) * PPH + nt * 8 + 2 * tt] = h1;
                }
            __syncwarp();

            // ---- O += P V ----
#pragma unroll
            for (int kq = 0; kq < 4; kq++) {
                unsigned a[2][4];
#pragma unroll
                for (int mt = 0; mt < 2; mt++)
                    ldsm4(a[mt][0], a[mt][1], a[mt][2], a[mt][3],
                          &Pw[(mt * 16 + a_row) * PPH + kq * 16 + a_col8]);
                unsigned vb[8][2];
#pragma unroll
                for (int np = 0; np < 4; np++)
                    ldsm4(vb[np * 2][0], vb[np * 2][1], vb[np * 2 + 1][0], vb[np * 2 + 1][1],
                          &Vcur[(np * 16 + b_row) * VPH + hk + kq * 16 + b_col8]);
#pragma unroll
                for (int mt = 0; mt < 2; mt++)
#pragma unroll
                    for (int nt = 0; nt < 8; nt++)
                        mma16(Of[mt][nt], a[mt][0], a[mt][1], a[mt][2], a[mt][3],
                              vb[nt][0], vb[nt][1]);
            }
        }
        __syncthreads();
    }

    const int b = bh >> 4, h = bh & 15;
#pragma unroll
    for (int mt = 0; mt < 2; mt++) {
        const float inv0 = 1.f / lrow[mt][0], inv1 = 1.f / lrow[mt][1];
        const int row = qt * 128 + warp * 32 + mt * 16 + g;
#pragma unroll
        for (int nt = 0; nt < 8; nt++) {
            size_t base  = ((size_t)(b * SEQ + row))     * D_MODEL + h * 64 + nt * 8 + 2 * tt;
            size_t base2 = ((size_t)(b * SEQ + row + 8)) * D_MODEL + h * 64 + nt * 8 + 2 * tt;
            *(__half2*)&g_ctx[base]  = __floats2half2_rn(Of[mt][nt][0] * inv0,
                                                         Of[mt][nt][1] * inv0);
            *(__half2*)&g_ctx[base2] = __floats2half2_rn(Of[mt][nt][2] * inv1,
                                                         Of[mt][nt][3] * inv1);
        }
    }
}

extern "C" void kernel_launch(void* const* d_in, const int* in_sizes, int n_in,
                              void* d_out, int out_size)
{
    const float* query = (const float*)d_in[0];
    const float* key   = (const float*)d_in[1];
    const float* value = (const float*)d_in[2];
    const float* Wq    = (const float*)d_in[3];
    const float* bq    = (const float*)d_in[4];
    const float* Wk    = (const float*)d_in[5];
    const float* bk    = (const float*)d_in[6];
    const float* Wv    = (const float*)d_in[7];
    const float* bv    = (const float*)d_in[8];
    const float* Wo    = (const float*)d_in[9];
    const float* bo    = (const float*)d_in[10];
    float* out = (float*)d_out;

    __half *hq, *hk, *hv, *hwq, *hwk, *hwv, *hwo, *gQ, *gK, *gV, *gC;
    cudaGetSymbolAddress((void**)&hq,  h_q);
    cudaGetSymbolAddress((void**)&hk,  h_k);
    cudaGetSymbolAddress((void**)&hv,  h_v);
    cudaGetSymbolAddress((void**)&hwq, h_wq);
    cudaGetSymbolAddress((void**)&hwk, h_wk);
    cudaGetSymbolAddress((void**)&hwv, h_wv);
    cudaGetSymbolAddress((void**)&hwo, h_wo);
    cudaGetSymbolAddress((void**)&gQ,  g_Q);
    cudaGetSymbolAddress((void**)&gK,  g_K);
    cudaGetSymbolAddress((void**)&gV,  g_V);
    cudaGetSymbolAddress((void**)&gC,  g_ctx);

    cudaFuncSetAttribute(attn_f16, cudaFuncAttributeMaxDynamicSharedMemorySize,
                         ATTN_SMEM_BYTES);
    cudaFuncSetAttribute(gemm_f16p, cudaFuncAttributeMaxDynamicSharedMemorySize,
                         GEMM_SMEM_BYTES);

    // 1) convert everything to fp16 (one launch)
    CvtJobs cj;
    cj.src[0] = query; cj.dst[0] = hq;  cj.n[0] = MTOT * D_MODEL;
    cj.src[1] = key;   cj.dst[1] = hk;  cj.n[1] = MTOT * D_MODEL;
    cj.src[2] = value; cj.dst[2] = hv;  cj.n[2] = MTOT * D_MODEL;
    cj.src[3] = Wq;    cj.dst[3] = hwq; cj.n[3] = D_MODEL * D_MODEL;
    cj.src[4] = Wk;    cj.dst[4] = hwk; cj.n[4] = D_MODEL * D_MODEL;
    cj.src[5] = Wv;    cj.dst[5] = hwv; cj.n[5] = D_MODEL * D_MODEL;
    cj.src[6] = Wo;    cj.dst[6] = hwo; cj.n[6] = D_MODEL * D_MODEL;
    cvt_f16<<<dim3(MTOT * D_MODEL / (256 * 8), 7), 256>>>(cj);

    // 2) fused Q/K/V projections
    GemmJobs3 qkv;
    qkv.j[0] = { hq, hwq, bq, gQ, 1, 0.125f * LOG2E };
    qkv.j[1] = { hk, hwk, bk, gK, 1, 1.0f };
    qkv.j[2] = { hv, hwv, bv, gV, 2, 1.0f };
    gemm_f16p<<<dim3(MTOT / 128, D_MODEL / 128, 3), 256, GEMM_SMEM_BYTES>>>(qkv);

    // 3) attention (Br=128, 4 warps x 32 q rows)
    dim3 agrid(SEQ / 128, BATCH * NUM_HEADS);
    attn_f16<<<agrid, 128, ATTN_SMEM_BYTES>>>();

    // 4) output projection
    GemmJobs3 oj;
    oj.j[0] = { gC, hwo, bo, out, 0, 1.0f };
    oj.j[1] = oj.j[0]; oj.j[2] = oj.j[0];
    gemm_f16p<<<dim3(MTOT / 128, D_MODEL / 128, 1), 256, GEMM_SMEM_BYTES>>>(oj);
}